// round 7
// baseline (speedup 1.0000x reference)
#include <cuda_runtime.h>
#include <math.h>
#include <stdint.h>

// ===========================================================================
// MMSSL forward — tf32 mma.sync, paired-A smem edition (race-fixed).
//  - A: LDG -> RNA-round -> paired-k STS (float2 (k,k+4)) -> 2x LDS.64 frags
//  - B: cp.async, pre-rounded in GMEM
//  - ONE syncthreads per ktile; ALL smem writes for buf^1 occur after the
//    barrier, all reads of buf^1 occurred before it (no producer overrun).
// ===========================================================================

#define UDIM 8192
#define IDIM 4096

static constexpr float MODEL_CAT = 0.55f;
static constexpr float ID_CAT    = 0.36f;

// ---- output offsets (floats) ----
static constexpr size_t OFF_UG_A  = 0;
static constexpr size_t OFF_IG_A  = 524288;
static constexpr size_t OFF_IIF   = 786432;
static constexpr size_t OFF_TIF   = 1048576;
static constexpr size_t OFF_IUF   = 1310720;
static constexpr size_t OFF_TUF   = 1835008;
static constexpr size_t OFF_UG_B  = 2359296;
static constexpr size_t OFF_IG_B  = 2883584;
static constexpr size_t OFF_IUID  = 3145728;
static constexpr size_t OFF_TUID  = 3670016;

// ---- scratch (floats); [0, S_ZERO_END) is atomic-accumulated, zeroed ----
static constexpr size_t S_IMGF  = 0;
static constexpr size_t S_TXTF  = 262144;
static constexpr size_t S_IIID  = 524288;
static constexpr size_t S_TIID  = 786432;
static constexpr size_t S_UG1   = 1048576;
static constexpr size_t S_UG2   = 1572864;
static constexpr size_t S_IG1   = 2097152;
static constexpr size_t S_IG2   = 2359296;
static constexpr size_t S_ZERO_END = 2621440;
static constexpr size_t S_UG0   = 2621440;
static constexpr size_t S_IG0   = 3145728;
// rounded-B buffers
static constexpr size_t S_RWIMG = 3407872;
static constexpr size_t S_RWTXT = 3670016;
static constexpr size_t S_RIID  = 3735552;
static constexpr size_t S_RUID  = 3997696;
static constexpr size_t S_RB3   = 4521984;
static constexpr size_t S_RIG0  = 5570560;
static constexpr size_t S_RUG1  = 5832704;
static constexpr size_t S_RIG1  = 6356992;
static constexpr size_t S_RUG2  = 6881280;
static constexpr size_t S_TOTAL = 7405568;

__device__ float g_scratch[S_TOTAL];

// ===========================================================================
__device__ __forceinline__ float rna_tf32(float x) {
    float r;
    asm("cvt.rna.tf32.f32 %0, %1;" : "=f"(r) : "f"(x));
    return r;
}
__device__ __forceinline__ uint32_t s2u(const void* p) {
    uint32_t a;
    asm("{ .reg .u64 t; cvta.to.shared.u64 t, %1; cvt.u32.u64 %0, t; }"
        : "=r"(a) : "l"(p));
    return a;
}
__device__ __forceinline__ void cp16(uint32_t s, const void* g) {
    asm volatile("cp.async.cg.shared.global [%0], [%1], 16;"
                 :: "r"(s), "l"(g) : "memory");
}
__device__ __forceinline__ float lds_f(uint32_t a) {
    float v;
    asm volatile("ld.shared.f32 %0, [%1];" : "=f"(v) : "r"(a));
    return v;
}
__device__ __forceinline__ float2 lds_f2(uint32_t a) {
    float2 v;
    asm volatile("ld.shared.v2.f32 {%0,%1}, [%2];" : "=f"(v.x), "=f"(v.y) : "r"(a));
    return v;
}
__device__ __forceinline__ void sts_f2(uint32_t a, float x, float y) {
    asm volatile("st.shared.v2.f32 [%0], {%1,%2};" :: "r"(a), "f"(x), "f"(y) : "memory");
}
__device__ __forceinline__ void mma8(float* d,
                                     uint32_t a0, uint32_t a1, uint32_t a2, uint32_t a3,
                                     uint32_t b0, uint32_t b1) {
    asm volatile(
        "mma.sync.aligned.m16n8k8.row.col.f32.tf32.tf32.f32 "
        "{%0,%1,%2,%3}, {%4,%5,%6,%7}, {%8,%9}, {%0,%1,%2,%3};\n"
        : "+f"(d[0]), "+f"(d[1]), "+f"(d[2]), "+f"(d[3])
        : "r"(a0), "r"(a1), "r"(a2), "r"(a3), "r"(b0), "r"(b1));
}

// ===========================================================================
struct GJob {
    const float* A;
    const float* B;
    const float* bias;
    float* C;
    int M;
    int K;
};
struct GJobs6 { GJob j[6]; };

// ---- shared layout constants ----
static constexpr uint32_t APBUF   = 16u * 132u * 8u;       // 16896
static constexpr uint32_t BBUF64  = 32u * 288u;            // 9216
static constexpr uint32_t STAGE64 = APBUF + BBUF64;        // 26112
static constexpr uint32_t SMEM64  = 2u * STAGE64;          // 52224
static constexpr uint32_t BBUF128 = 32u * 544u;            // 17408
static constexpr uint32_t STAGE128 = APBUF + BBUF128;      // 34304
static constexpr uint32_t SMEM128  = 2u * STAGE128;        // 68608

// ---------------- N=64 GEMM (128 threads, 4 CTAs/SM) ----------------------
__global__ __launch_bounds__(128, 4) void gemm_cp(GJobs6 P)
{
    extern __shared__ char sm[];
    const GJob jb = P.j[blockIdx.z];
    const int mb = blockIdx.x * 128;
    if (mb >= jb.M) return;
    const int K = jb.K;
    const int chunk = K / (int)gridDim.y;
    const int k0 = (int)blockIdx.y * chunk;
    const int nt = chunk >> 5;

    const int tid  = threadIdx.x;
    const int lane = tid & 31;
    const int wid  = tid >> 5;
    const int gid  = lane >> 2;
    const int tig  = lane & 3;
    const int wm   = (wid & 1) * 64;
    const int wn   = (wid >> 1) * 32;

    const uint32_t sb = s2u(sm);
    const int ar0 = tid >> 1;
    const int akc = (tid & 1) * 16;
    const int pb0 = (tid & 1) * 8;
    const float* __restrict__ Ag = jb.A + (size_t)mb * K + k0 + akc;
    const float* __restrict__ Bg = jb.B + (size_t)k0 * 64;
    const int bk  = tid >> 2;
    const int bs  = (tid & 3) * 4;

    float acc[4][4][4];
#pragma unroll
    for (int m = 0; m < 4; m++)
#pragma unroll
        for (int j = 0; j < 4; j++)
#pragma unroll
            for (int c = 0; c < 4; c++) acc[m][j][c] = 0.f;

    float4 av[4];

    auto LDGA = [&](int t, int ch) {
        const float* p = Ag + (size_t)(ar0 + 64 * ch) * K + t * 32;
#pragma unroll
        for (int i = 0; i < 4; i++)
            av[i] = *reinterpret_cast<const float4*>(p + 4 * i);
    };
    auto STSA = [&](int buf, int ch) {
        const uint32_t ab = sb + (uint32_t)buf * STAGE64;
        const int row = ar0 + 64 * ch;
#pragma unroll
        for (int i2 = 0; i2 < 2; i2++) {
            const float* lo = &av[2 * i2].x;
            const float* hi = &av[2 * i2 + 1].x;
#pragma unroll
            for (int j = 0; j < 4; j++) {
                int p = pb0 + i2 * 4 + j;
                sts_f2(ab + (uint32_t)((p * 132 + row) << 3),
                       rna_tf32(lo[j]), rna_tf32(hi[j]));
            }
        }
    };
    auto CPB = [&](int t, int buf) {
        const uint32_t bb = sb + (uint32_t)buf * STAGE64 + APBUF;
        const float* Bt = Bg + (size_t)t * 32 * 64;
#pragma unroll
        for (int i = 0; i < 4; i++)
            cp16(bb + (uint32_t)(bk * 288 + (bs + i) * 16),
                 Bt + (size_t)bk * 64 + (bs + i) * 4);
        asm volatile("cp.async.commit_group;" ::: "memory");
    };

    auto COMP2 = [&](int buf, int ksb) {
        const uint32_t ab = sb + (uint32_t)buf * STAGE64;
        const uint32_t bb = ab + APBUF;
#pragma unroll
        for (int ks = ksb; ks < ksb + 2; ks++) {
            const int p = ks * 4 + tig;
            uint32_t a0[4], a1[4], a2[4], a3[4];
#pragma unroll
            for (int mt = 0; mt < 4; mt++) {
                int row = wm + mt * 16 + gid;
                float2 lo = lds_f2(ab + (uint32_t)((p * 132 + row) << 3));
                float2 hi = lds_f2(ab + (uint32_t)((p * 132 + row + 8) << 3));
                a0[mt] = __float_as_uint(lo.x);
                a2[mt] = __float_as_uint(lo.y);
                a1[mt] = __float_as_uint(hi.x);
                a3[mt] = __float_as_uint(hi.y);
            }
#pragma unroll
            for (int j = 0; j < 4; j++) {
                int col = wn + j * 8 + gid;
                uint32_t b0 = __float_as_uint(
                    lds_f(bb + (uint32_t)(((ks * 8 + tig) * 72 + col) << 2)));
                uint32_t b1 = __float_as_uint(
                    lds_f(bb + (uint32_t)(((ks * 8 + tig + 4) * 72 + col) << 2)));
#pragma unroll
                for (int mt = 0; mt < 4; mt++)
                    mma8(acc[mt][j], a0[mt], a1[mt], a2[mt], a3[mt], b0, b1);
            }
        }
    };

    // prologue: fill buffer 0
    LDGA(0, 0); STSA(0, 0);
    LDGA(0, 1); STSA(0, 1);
    CPB(0, 0);

    for (int t = 0; t < nt; t++) {
        const int buf = t & 1;
        const bool more = (t + 1 < nt);
        // drain CPB(t) — issued one full iteration ago
        asm volatile("cp.async.wait_group 0;" ::: "memory");
        __syncthreads();
        // ALL writes to buf^1 happen after this barrier; all reads of buf^1
        // (iteration t-1's COMP) happened before it.
        if (more) {
            CPB(t + 1, buf ^ 1);
            LDGA(t + 1, 0);
        }
        COMP2(buf, 0);
        if (more) { STSA(buf ^ 1, 0); LDGA(t + 1, 1); }
        COMP2(buf, 2);
        if (more) STSA(buf ^ 1, 1);
    }

    const bool addb = (blockIdx.y == 0) && (jb.bias != nullptr);
#pragma unroll
    for (int mt = 0; mt < 4; mt++) {
#pragma unroll
        for (int j = 0; j < 4; j++) {
            int row = mb + wm + mt * 16 + gid;
            int col = wn + j * 8 + 2 * tig;
            float b0 = addb ? jb.bias[col] : 0.f;
            float b1 = addb ? jb.bias[col + 1] : 0.f;
            atomicAdd(jb.C + (size_t)row * 64 + col,           acc[mt][j][0] + b0);
            atomicAdd(jb.C + (size_t)row * 64 + col + 1,       acc[mt][j][1] + b1);
            atomicAdd(jb.C + (size_t)(row + 8) * 64 + col,     acc[mt][j][2] + b0);
            atomicAdd(jb.C + (size_t)(row + 8) * 64 + col + 1, acc[mt][j][3] + b1);
        }
    }
}

// ---------------- N=128 GEMM (256 threads): A read once, two B/C -----------
struct G128 {
    const float* A;
    const float* B1;
    const float* B2;
    float* C1;
    float* C2;
    int M;
    int K;
};

__global__ __launch_bounds__(256, 2) void gemm128(G128 jb)
{
    extern __shared__ char sm[];
    const int mb = blockIdx.x * 128;
    const int K = jb.K;
    const int chunk = K / (int)gridDim.y;
    const int k0 = (int)blockIdx.y * chunk;
    const int nt = chunk >> 5;

    const int tid  = threadIdx.x;
    const int lane = tid & 31;
    const int wid  = tid >> 5;
    const int gid  = lane >> 2;
    const int tig  = lane & 3;
    const int wm   = (wid & 1) * 64;
    const int wn   = (wid >> 1) * 32;

    const uint32_t sb = s2u(sm);
    const int ar = tid >> 1;
    const int akc = (tid & 1) * 16;
    const int pb0 = (tid & 1) * 8;
    const float* __restrict__ Ag = jb.A + (size_t)(mb + ar) * K + k0 + akc;
    const float* __restrict__ B1 = jb.B1 + (size_t)k0 * 64;
    const float* __restrict__ B2 = jb.B2 + (size_t)k0 * 64;
    const int bk = tid >> 3;
    const int bs = tid & 7;

    float acc[4][4][4];
#pragma unroll
    for (int m = 0; m < 4; m++)
#pragma unroll
        for (int j = 0; j < 4; j++)
#pragma unroll
            for (int c = 0; c < 4; c++) acc[m][j][c] = 0.f;

    float4 av[4];

    auto LDGA = [&](int t) {
        const float* p = Ag + t * 32;
#pragma unroll
        for (int i = 0; i < 4; i++)
            av[i] = *reinterpret_cast<const float4*>(p + 4 * i);
    };
    auto STSA = [&](int buf) {
        const uint32_t ab = sb + (uint32_t)buf * STAGE128;
#pragma unroll
        for (int i2 = 0; i2 < 2; i2++) {
            const float* lo = &av[2 * i2].x;
            const float* hi = &av[2 * i2 + 1].x;
#pragma unroll
            for (int j = 0; j < 4; j++) {
                int p = pb0 + i2 * 4 + j;
                sts_f2(ab + (uint32_t)((p * 132 + ar) << 3),
                       rna_tf32(lo[j]), rna_tf32(hi[j]));
            }
        }
    };
    auto CPB = [&](int t, int buf) {
        const uint32_t bb = sb + (uint32_t)buf * STAGE128 + APBUF;
#pragma unroll
        for (int i = 0; i < 4; i++) {
            int s = bs + 8 * i;
            const float* src = (s < 16)
                ? (jb.B1 + (size_t)(k0 + t * 32 + bk) * 64 + s * 4)
                : (jb.B2 + (size_t)(k0 + t * 32 + bk) * 64 + (s - 16) * 4);
            cp16(bb + (uint32_t)(bk * 544 + s * 16), src);
        }
        asm volatile("cp.async.commit_group;" ::: "memory");
    };
    (void)B1; (void)B2;

    auto COMP2 = [&](int buf, int ksb) {
        const uint32_t ab = sb + (uint32_t)buf * STAGE128;
        const uint32_t bb = ab + APBUF;
#pragma unroll
        for (int ks = ksb; ks < ksb + 2; ks++) {
            const int p = ks * 4 + tig;
            uint32_t a0[4], a1[4], a2[4], a3[4];
#pragma unroll
            for (int mt = 0; mt < 4; mt++) {
                int row = wm + mt * 16 + gid;
                float2 lo = lds_f2(ab + (uint32_t)((p * 132 + row) << 3));
                float2 hi = lds_f2(ab + (uint32_t)((p * 132 + row + 8) << 3));
                a0[mt] = __float_as_uint(lo.x);
                a2[mt] = __float_as_uint(lo.y);
                a1[mt] = __float_as_uint(hi.x);
                a3[mt] = __float_as_uint(hi.y);
            }
#pragma unroll
            for (int j = 0; j < 4; j++) {
                int col = wn + j * 8 + gid;
                uint32_t b0 = __float_as_uint(
                    lds_f(bb + (uint32_t)(((ks * 8 + tig) * 136 + col) << 2)));
                uint32_t b1 = __float_as_uint(
                    lds_f(bb + (uint32_t)(((ks * 8 + tig + 4) * 136 + col) << 2)));
#pragma unroll
                for (int mt = 0; mt < 4; mt++)
                    mma8(acc[mt][j], a0[mt], a1[mt], a2[mt], a3[mt], b0, b1);
            }
        }
    };

    LDGA(0); STSA(0);
    CPB(0, 0);

    for (int t = 0; t < nt; t++) {
        const int buf = t & 1;
        const bool more = (t + 1 < nt);
        asm volatile("cp.async.wait_group 0;" ::: "memory");
        __syncthreads();
        if (more) {
            CPB(t + 1, buf ^ 1);
            LDGA(t + 1);
        }
        COMP2(buf, 0);
        if (more) STSA(buf ^ 1);
        COMP2(buf, 2);
    }

#pragma unroll
    for (int mt = 0; mt < 4; mt++) {
#pragma unroll
        for (int j = 0; j < 4; j++) {
            int row = mb + wm + mt * 16 + gid;
            int col = wn + j * 8 + 2 * tig;
            float* C = (col < 64) ? jb.C1 : jb.C2;
            int cc = col & 63;
            atomicAdd(C + (size_t)row * 64 + cc,           acc[mt][j][0]);
            atomicAdd(C + (size_t)row * 64 + cc + 1,       acc[mt][j][1]);
            atomicAdd(C + (size_t)(row + 8) * 64 + cc,     acc[mt][j][2]);
            atomicAdd(C + (size_t)(row + 8) * 64 + cc + 1, acc[mt][j][3]);
        }
    }
}

// ===========================================================================
// batched elementwise RNA round
// ===========================================================================
struct RJob { const float* s; float* d; int n; };
struct RJobs4 { RJob j[4]; };

__global__ __launch_bounds__(256) void round_batch(RJobs4 P)
{
    const RJob jb = P.j[blockIdx.z];
    int i = blockIdx.x * 256 + threadIdx.x;
    int stride = gridDim.x * 256;
    for (; i < jb.n; i += stride) jb.d[i] = rna_tf32(jb.s[i]);
}

// ===========================================================================
// MHSA over the 2-modality axis fused with mean/norm/id-add
// ===========================================================================
__global__ __launch_bounds__(256) void mhsa_kernel(
    const float* __restrict__ xi, const float* __restrict__ xt,
    const float* __restrict__ idemb,
    const float* __restrict__ wq, const float* __restrict__ wk,
    const float* __restrict__ wcat,
    float* __restrict__ outp, float* __restrict__ outr, int M)
{
    __shared__ float sx[8][2][64];
    __shared__ float sqk[8][4][64];
    __shared__ float satt[8][16];
    const int warp = threadIdx.x >> 5;
    const int lane = threadIdx.x & 31;
    const int gw = blockIdx.x * 8 + warp;
    const int nw = gridDim.x * 8;

    for (int n = gw; n < M; n += nw) {
        sx[warp][0][lane]      = xi[(size_t)n * 64 + lane];
        sx[warp][0][lane + 32] = xi[(size_t)n * 64 + lane + 32];
        sx[warp][1][lane]      = xt[(size_t)n * 64 + lane];
        sx[warp][1][lane + 32] = xt[(size_t)n * 64 + lane + 32];
        __syncwarp();

        float qi0=0,qi1=0,ki0=0,ki1=0,qt0=0,qt1=0,kt0=0,kt1=0;
        float pi[4][2] = {}, pt[4][2] = {};
#pragma unroll 4
        for (int k = 0; k < 64; k++) {
            float xik = sx[warp][0][k];
            float xtk = sx[warp][1][k];
            float wq0 = wq[k * 64 + lane],      wq1 = wq[k * 64 + lane + 32];
            float wk0 = wk[k * 64 + lane],      wk1 = wk[k * 64 + lane + 32];
            qi0 = fmaf(xik, wq0, qi0); qi1 = fmaf(xik, wq1, qi1);
            ki0 = fmaf(xik, wk0, ki0); ki1 = fmaf(xik, wk1, ki1);
            qt0 = fmaf(xtk, wq0, qt0); qt1 = fmaf(xtk, wq1, qt1);
            kt0 = fmaf(xtk, wk0, kt0); kt1 = fmaf(xtk, wk1, kt1);
#pragma unroll
            for (int h = 0; h < 4; h++) {
                float wc0 = wcat[(h * 64 + k) * 64 + lane];
                float wc1 = wcat[(h * 64 + k) * 64 + lane + 32];
                pi[h][0] = fmaf(xik, wc0, pi[h][0]);
                pi[h][1] = fmaf(xik, wc1, pi[h][1]);
                pt[h][0] = fmaf(xtk, wc0, pt[h][0]);
                pt[h][1] = fmaf(xtk, wc1, pt[h][1]);
            }
        }
        sqk[warp][0][lane] = qi0; sqk[warp][0][lane + 32] = qi1;
        sqk[warp][1][lane] = ki0; sqk[warp][1][lane + 32] = ki1;
        sqk[warp][2][lane] = qt0; sqk[warp][2][lane + 32] = qt1;
        sqk[warp][3][lane] = kt0; sqk[warp][3][lane + 32] = kt1;
        __syncwarp();

        {
            int cc = lane & 15;
            int h = cc >> 2, a = (cc >> 1) & 1, b = cc & 1;
            const float* qv = &sqk[warp][a * 2][h * 16];
            const float* kv = &sqk[warp][1 + b * 2][h * 16];
            float l = 0.f;
#pragma unroll
            for (int u = 0; u < 16; u++) l = fmaf(qv[u], kv[u], l);
            l *= 0.25f;
            float lo = __shfl_xor_sync(0xffffffffu, l, 1);
            float mm = fmaxf(l, lo);
            float e  = expf(l - mm);
            float eo = __shfl_xor_sync(0xffffffffu, e, 1);
            float att = e / (e + eo);
            if (lane < 16) satt[warp][lane] = att;
        }
        __syncwarp();

        float z0 = 0.f, z1 = 0.f;
#pragma unroll
        for (int h = 0; h < 4; h++) {
            float cih = 0.5f * (satt[warp][h * 4 + 0] + satt[warp][h * 4 + 2]);
            float cth = 0.5f * (satt[warp][h * 4 + 1] + satt[warp][h * 4 + 3]);
            z0 = fmaf(cih, pi[h][0], fmaf(cth, pt[h][0], z0));
            z1 = fmaf(cih, pi[h][1], fmaf(cth, pt[h][1], z1));
        }
        float ss = z0 * z0 + z1 * z1;
#pragma unroll
        for (int o = 16; o; o >>= 1) ss += __shfl_xor_sync(0xffffffffu, ss, o);
        float scale = ID_CAT / fmaxf(sqrtf(ss), 1e-12f);
        float r0 = idemb[(size_t)n * 64 + lane]      + z0 * scale;
        float r1 = idemb[(size_t)n * 64 + lane + 32] + z1 * scale;
        outp[(size_t)n * 64 + lane]      = r0;
        outp[(size_t)n * 64 + lane + 32] = r1;
        if (outr) {
            outr[(size_t)n * 64 + lane]      = rna_tf32(r0);
            outr[(size_t)n * 64 + lane + 32] = rna_tf32(r1);
        }
        __syncwarp();
    }
}

// row softmax; optional rounded copy
__global__ __launch_bounds__(256) void softmax_kernel(
    float* __restrict__ X, float* __restrict__ outr, int M)
{
    const int warp = threadIdx.x >> 5;
    const int lane = threadIdx.x & 31;
    const int gw = blockIdx.x * 8 + warp;
    const int nw = gridDim.x * 8;
    for (int n = gw; n < M; n += nw) {
        size_t i = (size_t)n * 64 + lane;
        float v0 = X[i], v1 = X[i + 32];
        float m = fmaxf(v0, v1);
#pragma unroll
        for (int o = 16; o; o >>= 1) m = fmaxf(m, __shfl_xor_sync(0xffffffffu, m, o));
        float e0 = expf(v0 - m), e1 = expf(v1 - m);
        float s = e0 + e1;
#pragma unroll
        for (int o = 16; o; o >>= 1) s += __shfl_xor_sync(0xffffffffu, s, o);
        float inv = 1.0f / s;
        float r0 = e0 * inv, r1 = e1 * inv;
        X[i] = r0;
        X[i + 32] = r1;
        if (outr) {
            outr[i] = rna_tf32(r0);
            outr[i + 32] = rna_tf32(r1);
        }
    }
}

__global__ __launch_bounds__(256) void epilogue_kernel(
    const float* __restrict__ g0, const float* __restrict__ g1,
    const float* __restrict__ g2,
    const float* __restrict__ fA, const float* __restrict__ fB,
    float* __restrict__ o1, float* __restrict__ o2, int M)
{
    const int warp = threadIdx.x >> 5;
    const int lane = threadIdx.x & 31;
    const int gw = blockIdx.x * 8 + warp;
    const int nw = gridDim.x * 8;
    for (int n = gw; n < M; n += nw) {
        size_t i = (size_t)n * 64 + lane;
        size_t i2 = i + 32;
        float m0 = (g0[i]  + g1[i]  + g2[i])  * (1.0f / 3.0f);
        float m1 = (g0[i2] + g1[i2] + g2[i2]) * (1.0f / 3.0f);
        float a0 = fA[i], a1 = fA[i2];
        float ssa = a0 * a0 + a1 * a1;
#pragma unroll
        for (int o = 16; o; o >>= 1) ssa += __shfl_xor_sync(0xffffffffu, ssa, o);
        float sA = MODEL_CAT / fmaxf(sqrtf(ssa), 1e-12f);
        float b0 = fB[i], b1 = fB[i2];
        float ssb = b0 * b0 + b1 * b1;
#pragma unroll
        for (int o = 16; o; o >>= 1) ssb += __shfl_xor_sync(0xffffffffu, ssb, o);
        float sB = MODEL_CAT / fmaxf(sqrtf(ssb), 1e-12f);
        float r0 = m0 + a0 * sA + b0 * sB;
        float r1 = m1 + a1 * sA + b1 * sB;
        o1[i] = r0;  o1[i2] = r1;
        o2[i] = r0;  o2[i2] = r1;
    }
}

// ===========================================================================
extern "C" void kernel_launch(void* const* d_in, const int* in_sizes, int n_in,
                              void* d_out, int out_size)
{
    const float* ui      = (const float*)d_in[0];
    const float* iu      = (const float*)d_in[1];
    const float* img_ui  = (const float*)d_in[2];
    const float* img_iu  = (const float*)d_in[3];
    const float* txt_ui  = (const float*)d_in[4];
    const float* txt_iu  = (const float*)d_in[5];
    const float* imgF    = (const float*)d_in[6];
    const float* txtF    = (const float*)d_in[7];
    const float* W_img   = (const float*)d_in[8];
    const float* b_img   = (const float*)d_in[9];
    const float* W_txt   = (const float*)d_in[10];
    const float* b_txt   = (const float*)d_in[11];
    const float* uid     = (const float*)d_in[12];
    const float* iid     = (const float*)d_in[13];
    const float* w_q     = (const float*)d_in[14];
    const float* w_k     = (const float*)d_in[15];
    const float* w_cat   = (const float*)d_in[16];
    float* out = (float*)d_out;

    float* scr = nullptr;
    cudaGetSymbolAddress((void**)&scr, g_scratch);

    cudaFuncSetAttribute(gemm_cp, cudaFuncAttributeMaxDynamicSharedMemorySize,
                         (int)SMEM64);
    cudaFuncSetAttribute(gemm128, cudaFuncAttributeMaxDynamicSharedMemorySize,
                         (int)SMEM128);

    // zero atomic-accumulation targets (d_out is poisoned)
    cudaMemsetAsync(out, 0, (size_t)4194304 * sizeof(float));
    cudaMemsetAsync(scr, 0, S_ZERO_END * sizeof(float));

    // prep: round static B operands (one batched launch)
    RJobs4 R;
    R.j[0] = RJob{W_img, scr + S_RWIMG, 262144};
    R.j[1] = RJob{W_txt, scr + S_RWTXT, 65536};
    R.j[2] = RJob{iid,   scr + S_RIID,  262144};
    R.j[3] = RJob{uid,   scr + S_RUID,  524288};
    round_batch<<<dim3(128, 1, 4), 256>>>(R);

    // MEGA launch: G1 (projections) + G4a + G4b (id propagations), 6 jobs
    GJobs6 P;
    P.j[0] = GJob{imgF,   scr + S_RWIMG, b_img, scr + S_IMGF,   IDIM, 4096};
    P.j[1] = GJob{txtF,   scr + S_RWTXT, b_txt, scr + S_TXTF,   IDIM, 1024};
    P.j[2] = GJob{img_ui, scr + S_RIID, nullptr, out + OFF_IUID, UDIM, 4096};
    P.j[3] = GJob{txt_ui, scr + S_RIID, nullptr, out + OFF_TUID, UDIM, 4096};
    P.j[4] = GJob{img_iu, scr + S_RUID, nullptr, scr + S_IIID,   IDIM, 8192};
    P.j[5] = GJob{txt_iu, scr + S_RUID, nullptr, scr + S_TIID,   IDIM, 8192};
    gemm_cp<<<dim3(64, 4, 6), 128, SMEM64>>>(P);

    // round img_f|txt_f in place (contiguous)
    R.j[0] = RJob{scr + S_IMGF, scr + S_IMGF, 524288};
    round_batch<<<dim3(512, 1, 1), 256>>>(R);

    // G2: [imageUF|textUF] = ui @ [img_f|txt_f]  (ui read once)
    gemm128<<<dim3(64, 8, 1), 256, SMEM128>>>(
        G128{ui, scr + S_IMGF, scr + S_TXTF, out + OFF_IUF, out + OFF_TUF,
             UDIM, 4096});

    // rounded copies of UF for G3's B (contiguous in out)
    R.j[0] = RJob{out + OFF_IUF, scr + S_RB3, 1048576};
    round_batch<<<dim3(512, 1, 1), 256>>>(R);

    // G3: [imageIF|textIF] = iu @ [imageUF|textUF]  (iu read once)
    gemm128<<<dim3(32, 16, 1), 256, SMEM128>>>(
        G128{iu, scr + S_RB3, scr + S_RB3 + 524288, out + OFF_IIF, out + OFF_TIF,
             IDIM, 8192});

    // MHSA -> u_g0, i_g0 (i_g0 also emitted rounded for loop1 B)
    mhsa_kernel<<<1024, 256>>>(out + OFF_IUID, out + OFF_TUID, uid,
                               w_q, w_k, w_cat, scr + S_UG0, nullptr, UDIM);
    mhsa_kernel<<<512, 256>>>(scr + S_IIID, scr + S_TIID, iid,
                              w_q, w_k, w_cat, scr + S_IG0, scr + S_RIG0, IDIM);

    // propagation loop (N_UI = 2)
    P.j[0] = GJob{ui, scr + S_RIG0, nullptr, scr + S_UG1, UDIM, 4096};
    gemm_cp<<<dim3(64, 8, 1), 128, SMEM64>>>(P);
    R.j[0] = RJob{scr + S_UG1, scr + S_RUG1, 524288};
    round_batch<<<dim3(512, 1, 1), 256>>>(R);

    P.j[0] = GJob{iu, scr + S_RUG1, nullptr, scr + S_IG1, IDIM, 8192};
    gemm_cp<<<dim3(32, 16, 1), 128, SMEM64>>>(P);
    R.j[0] = RJob{scr + S_IG1, scr + S_RIG1, 262144};
    round_batch<<<dim3(256, 1, 1), 256>>>(R);

    P.j[0] = GJob{ui, scr + S_RIG1, nullptr, scr + S_UG2, UDIM, 4096};
    gemm_cp<<<dim3(64, 8, 1), 128, SMEM64>>>(P);
    softmax_kernel<<<1024, 256>>>(scr + S_UG2, scr + S_RUG2, UDIM);

    P.j[0] = GJob{iu, scr + S_RUG2, nullptr, scr + S_IG2, IDIM, 8192};
    gemm_cp<<<dim3(32, 16, 1), 128, SMEM64>>>(P);
    softmax_kernel<<<512, 256>>>(scr + S_IG2, nullptr, IDIM);

    // final combine
    epilogue_kernel<<<1024, 256>>>(scr + S_UG0, scr + S_UG1, scr + S_UG2,
                                   out + OFF_IUF, out + OFF_TUF,
                                   out + OFF_UG_A, out + OFF_UG_B, UDIM);
    epilogue_kernel<<<512, 256>>>(scr + S_IG0, scr + S_IG1, scr + S_IG2,
                                  out + OFF_IIF, out + OFF_TIF,
                                  out + OFF_IG_A, out + OFF_IG_B, IDIM);
}

// round 8
// speedup vs baseline: 1.3107x; 1.3107x over previous
#include <cuda_runtime.h>
#include <math.h>
#include <stdint.h>

// ===========================================================================
// MMSSL forward — tf32 mma.sync + cp.async (R5-proven GEMM core) with
// batched mhsa/epilogue launches.
// ===========================================================================

#define UDIM 8192
#define IDIM 4096

static constexpr float MODEL_CAT = 0.55f;
static constexpr float ID_CAT    = 0.36f;

// ---- output offsets (floats) ----
static constexpr size_t OFF_UG_A  = 0;
static constexpr size_t OFF_IG_A  = 524288;
static constexpr size_t OFF_IIF   = 786432;
static constexpr size_t OFF_TIF   = 1048576;
static constexpr size_t OFF_IUF   = 1310720;
static constexpr size_t OFF_TUF   = 1835008;
static constexpr size_t OFF_UG_B  = 2359296;
static constexpr size_t OFF_IG_B  = 2883584;
static constexpr size_t OFF_IUID  = 3145728;
static constexpr size_t OFF_TUID  = 3670016;

// ---- scratch (floats); [0, S_ZERO_END) is atomic-accumulated, zeroed ----
static constexpr size_t S_IMGF  = 0;
static constexpr size_t S_TXTF  = 262144;
static constexpr size_t S_IIID  = 524288;
static constexpr size_t S_TIID  = 786432;
static constexpr size_t S_UG1   = 1048576;
static constexpr size_t S_UG2   = 1572864;
static constexpr size_t S_IG1   = 2097152;
static constexpr size_t S_IG2   = 2359296;
static constexpr size_t S_ZERO_END = 2621440;
static constexpr size_t S_UG0   = 2621440;
static constexpr size_t S_IG0   = 3145728;
// rounded-B buffers
static constexpr size_t S_RWIMG = 3407872;
static constexpr size_t S_RWTXT = 3670016;
static constexpr size_t S_RIID  = 3735552;
static constexpr size_t S_RUID  = 3997696;
static constexpr size_t S_RB3   = 4521984;
static constexpr size_t S_RIG0  = 5570560;
static constexpr size_t S_RUG1  = 5832704;
static constexpr size_t S_RIG1  = 6356992;
static constexpr size_t S_RUG2  = 6881280;
static constexpr size_t S_TOTAL = 7405568;

__device__ float g_scratch[S_TOTAL];

// ===========================================================================
__device__ __forceinline__ float rna_tf32(float x) {
    float r;
    asm("cvt.rna.tf32.f32 %0, %1;" : "=f"(r) : "f"(x));
    return r;
}
__device__ __forceinline__ uint32_t s2u(const void* p) {
    uint32_t a;
    asm("{ .reg .u64 t; cvta.to.shared.u64 t, %1; cvt.u32.u64 %0, t; }"
        : "=r"(a) : "l"(p));
    return a;
}
__device__ __forceinline__ void cp16(uint32_t s, const void* g) {
    asm volatile("cp.async.cg.shared.global [%0], [%1], 16;"
                 :: "r"(s), "l"(g) : "memory");
}
__device__ __forceinline__ float lds_f(uint32_t a) {
    float v;
    asm volatile("ld.shared.f32 %0, [%1];" : "=f"(v) : "r"(a));
    return v;
}
__device__ __forceinline__ void mma8(float* d,
                                     uint32_t a0, uint32_t a1, uint32_t a2, uint32_t a3,
                                     uint32_t b0, uint32_t b1) {
    asm volatile(
        "mma.sync.aligned.m16n8k8.row.col.f32.tf32.tf32.f32 "
        "{%0,%1,%2,%3}, {%4,%5,%6,%7}, {%8,%9}, {%0,%1,%2,%3};\n"
        : "+f"(d[0]), "+f"(d[1]), "+f"(d[2]), "+f"(d[3])
        : "r"(a0), "r"(a1), "r"(a2), "r"(a3), "r"(b0), "r"(b1));
}

// ===========================================================================
// GEMM (R5-proven): C[M,64] += rna(A[M,K]) @ B_r[K,64]
// smem: A stage [128][36] f32 (rows 144B), B stage [32][72] f32 (rows 288B)
// ===========================================================================
struct GJob {
    const float* A;
    const float* B;
    const float* bias;
    float* C;
    int M;
    int K;
};
struct GJobs6 { GJob j[6]; };

static constexpr uint32_t ABUF_B  = 128u * 144u;          // 18432
static constexpr uint32_t BBUF_B  = 32u * 288u;           // 9216
static constexpr uint32_t STAGE_B = ABUF_B + BBUF_B;      // 27648
static constexpr uint32_t GEMM_SMEM = 2u * STAGE_B;       // 55296

__global__ __launch_bounds__(128, 4) void gemm_cp(GJobs6 P)
{
    extern __shared__ char sm[];
    const GJob jb = P.j[blockIdx.z];
    const int mb = blockIdx.x * 128;
    if (mb >= jb.M) return;
    const int K = jb.K;
    const int chunk = K / (int)gridDim.y;
    const int k0 = (int)blockIdx.y * chunk;
    const int nt = chunk >> 5;

    const int tid  = threadIdx.x;
    const int lane = tid & 31;
    const int wid  = tid >> 5;
    const int gid  = lane >> 2;
    const int tig  = lane & 3;
    const int wm   = (wid & 1) * 64;
    const int wn   = (wid >> 1) * 32;

    const uint32_t sb = s2u(sm);
    const float* __restrict__ Ag = jb.A + (size_t)mb * K + k0;
    const float* __restrict__ Bg = jb.B + (size_t)k0 * 64;

    float acc[4][4][4];
#pragma unroll
    for (int m = 0; m < 4; m++)
#pragma unroll
        for (int j = 0; j < 4; j++)
#pragma unroll
            for (int c = 0; c < 4; c++) acc[m][j][c] = 0.f;

    auto LOAD = [&](int t, int buf) {
        const uint32_t ab = sb + (uint32_t)buf * STAGE_B;
        const uint32_t bb = ab + ABUF_B;
        const float* At = Ag + t * 32;
        const float* Bt = Bg + (size_t)t * 32 * 64;
#pragma unroll
        for (int i = 0; i < 8; i++) {
            int c = i * 128 + tid;
            int row = c >> 3, seg = c & 7;
            cp16(ab + (uint32_t)(row * 144 + seg * 16),
                 At + (size_t)row * K + seg * 4);
        }
#pragma unroll
        for (int i = 0; i < 4; i++) {
            int c = i * 128 + tid;
            int k = c >> 4, seg = c & 15;
            cp16(bb + (uint32_t)(k * 288 + seg * 16),
                 Bt + (size_t)k * 64 + seg * 4);
        }
        asm volatile("cp.async.commit_group;" ::: "memory");
    };

    auto COMP = [&](int buf) {
        const uint32_t ab = sb + (uint32_t)buf * STAGE_B;
        const uint32_t bb = ab + ABUF_B;
#pragma unroll
        for (int ks = 0; ks < 4; ks++) {
            uint32_t a0[4], a1[4], a2[4], a3[4];
            const int k = ks * 8 + tig;
#pragma unroll
            for (int mt = 0; mt < 4; mt++) {
                int row = wm + mt * 16 + gid;
                float x0 = lds_f(ab + (uint32_t)((row * 36 + k) << 2));
                float x1 = lds_f(ab + (uint32_t)(((row + 8) * 36 + k) << 2));
                float x2 = lds_f(ab + (uint32_t)((row * 36 + k + 4) << 2));
                float x3 = lds_f(ab + (uint32_t)(((row + 8) * 36 + k + 4) << 2));
                a0[mt] = __float_as_uint(rna_tf32(x0));
                a1[mt] = __float_as_uint(rna_tf32(x1));
                a2[mt] = __float_as_uint(rna_tf32(x2));
                a3[mt] = __float_as_uint(rna_tf32(x3));
            }
#pragma unroll
            for (int j = 0; j < 4; j++) {
                int col = wn + j * 8 + gid;
                uint32_t b0 = __float_as_uint(
                    lds_f(bb + (uint32_t)(((ks * 8 + tig) * 72 + col) << 2)));
                uint32_t b1 = __float_as_uint(
                    lds_f(bb + (uint32_t)(((ks * 8 + tig + 4) * 72 + col) << 2)));
#pragma unroll
                for (int mt = 0; mt < 4; mt++)
                    mma8(acc[mt][j], a0[mt], a1[mt], a2[mt], a3[mt], b0, b1);
            }
        }
    };

    LOAD(0, 0);
    for (int t = 0; t < nt; t++) {
        const int buf = t & 1;
        if (t + 1 < nt) {
            LOAD(t + 1, buf ^ 1);
            asm volatile("cp.async.wait_group 1;" ::: "memory");
        } else {
            asm volatile("cp.async.wait_group 0;" ::: "memory");
        }
        __syncthreads();
        COMP(buf);
        __syncthreads();
    }

    const bool addb = (blockIdx.y == 0) && (jb.bias != nullptr);
#pragma unroll
    for (int mt = 0; mt < 4; mt++) {
#pragma unroll
        for (int j = 0; j < 4; j++) {
            int row = mb + wm + mt * 16 + gid;
            int col = wn + j * 8 + 2 * tig;
            float b0 = addb ? jb.bias[col] : 0.f;
            float b1 = addb ? jb.bias[col + 1] : 0.f;
            atomicAdd(jb.C + (size_t)row * 64 + col,           acc[mt][j][0] + b0);
            atomicAdd(jb.C + (size_t)row * 64 + col + 1,       acc[mt][j][1] + b1);
            atomicAdd(jb.C + (size_t)(row + 8) * 64 + col,     acc[mt][j][2] + b0);
            atomicAdd(jb.C + (size_t)(row + 8) * 64 + col + 1, acc[mt][j][3] + b1);
        }
    }
}

// ---------------- N=128 GEMM (256 threads): A read once, two B/C -----------
struct G128 {
    const float* A;
    const float* B1;
    const float* B2;
    float* C1;
    float* C2;
    int M;
    int K;
};

static constexpr uint32_t B128_B   = 32u * 544u;            // [32][136] f32
static constexpr uint32_t STAGE128 = ABUF_B + B128_B;       // 35840
static constexpr uint32_t SMEM128  = 2u * STAGE128;         // 71680

__global__ __launch_bounds__(256, 2) void gemm128(G128 jb)
{
    extern __shared__ char sm[];
    const int mb = blockIdx.x * 128;
    const int K = jb.K;
    const int chunk = K / (int)gridDim.y;
    const int k0 = (int)blockIdx.y * chunk;
    const int nt = chunk >> 5;

    const int tid  = threadIdx.x;
    const int lane = tid & 31;
    const int wid  = tid >> 5;
    const int gid  = lane >> 2;
    const int tig  = lane & 3;
    const int wm   = (wid & 1) * 64;
    const int wn   = (wid >> 1) * 32;

    const uint32_t sb = s2u(sm);
    const float* __restrict__ Ag = jb.A + (size_t)mb * K + k0;

    float acc[4][4][4];
#pragma unroll
    for (int m = 0; m < 4; m++)
#pragma unroll
        for (int j = 0; j < 4; j++)
#pragma unroll
            for (int c = 0; c < 4; c++) acc[m][j][c] = 0.f;

    auto LOAD = [&](int t, int buf) {
        const uint32_t ab = sb + (uint32_t)buf * STAGE128;
        const uint32_t bb = ab + ABUF_B;
        const float* At = Ag + t * 32;
#pragma unroll
        for (int i = 0; i < 4; i++) {
            int c = i * 256 + tid;
            int row = c >> 3, seg = c & 7;
            cp16(ab + (uint32_t)(row * 144 + seg * 16),
                 At + (size_t)row * K + seg * 4);
        }
#pragma unroll
        for (int i = 0; i < 4; i++) {
            int c = i * 256 + tid;
            int k = c >> 5, seg = c & 31;
            const float* src = (seg < 16)
                ? (jb.B1 + (size_t)(k0 + t * 32 + k) * 64 + seg * 4)
                : (jb.B2 + (size_t)(k0 + t * 32 + k) * 64 + (seg - 16) * 4);
            cp16(bb + (uint32_t)(k * 544 + seg * 16), src);
        }
        asm volatile("cp.async.commit_group;" ::: "memory");
    };

    auto COMP = [&](int buf) {
        const uint32_t ab = sb + (uint32_t)buf * STAGE128;
        const uint32_t bb = ab + ABUF_B;
#pragma unroll
        for (int ks = 0; ks < 4; ks++) {
            uint32_t a0[4], a1[4], a2[4], a3[4];
            const int k = ks * 8 + tig;
#pragma unroll
            for (int mt = 0; mt < 4; mt++) {
                int row = wm + mt * 16 + gid;
                float x0 = lds_f(ab + (uint32_t)((row * 36 + k) << 2));
                float x1 = lds_f(ab + (uint32_t)(((row + 8) * 36 + k) << 2));
                float x2 = lds_f(ab + (uint32_t)((row * 36 + k + 4) << 2));
                float x3 = lds_f(ab + (uint32_t)(((row + 8) * 36 + k + 4) << 2));
                a0[mt] = __float_as_uint(rna_tf32(x0));
                a1[mt] = __float_as_uint(rna_tf32(x1));
                a2[mt] = __float_as_uint(rna_tf32(x2));
                a3[mt] = __float_as_uint(rna_tf32(x3));
            }
#pragma unroll
            for (int j = 0; j < 4; j++) {
                int col = wn + j * 8 + gid;
                uint32_t b0 = __float_as_uint(
                    lds_f(bb + (uint32_t)(((ks * 8 + tig) * 136 + col) << 2)));
                uint32_t b1 = __float_as_uint(
                    lds_f(bb + (uint32_t)(((ks * 8 + tig + 4) * 136 + col) << 2)));
#pragma unroll
                for (int mt = 0; mt < 4; mt++)
                    mma8(acc[mt][j], a0[mt], a1[mt], a2[mt], a3[mt], b0, b1);
            }
        }
    };

    LOAD(0, 0);
    for (int t = 0; t < nt; t++) {
        const int buf = t & 1;
        if (t + 1 < nt) {
            LOAD(t + 1, buf ^ 1);
            asm volatile("cp.async.wait_group 1;" ::: "memory");
        } else {
            asm volatile("cp.async.wait_group 0;" ::: "memory");
        }
        __syncthreads();
        COMP(buf);
        __syncthreads();
    }

#pragma unroll
    for (int mt = 0; mt < 4; mt++) {
#pragma unroll
        for (int j = 0; j < 4; j++) {
            int row = mb + wm + mt * 16 + gid;
            int col = wn + j * 8 + 2 * tig;
            float* C = (col < 64) ? jb.C1 : jb.C2;
            int cc = col & 63;
            atomicAdd(C + (size_t)row * 64 + cc,           acc[mt][j][0]);
            atomicAdd(C + (size_t)row * 64 + cc + 1,       acc[mt][j][1]);
            atomicAdd(C + (size_t)(row + 8) * 64 + cc,     acc[mt][j][2]);
            atomicAdd(C + (size_t)(row + 8) * 64 + cc + 1, acc[mt][j][3]);
        }
    }
}

// ===========================================================================
// batched elementwise RNA round
// ===========================================================================
struct RJob { const float* s; float* d; int n; };
struct RJobs4 { RJob j[4]; };

__global__ __launch_bounds__(256) void round_batch(RJobs4 P)
{
    const RJob jb = P.j[blockIdx.z];
    int i = blockIdx.x * 256 + threadIdx.x;
    int stride = gridDim.x * 256;
    for (; i < jb.n; i += stride) jb.d[i] = rna_tf32(jb.s[i]);
}

// ===========================================================================
// MHSA over the 2-modality axis fused with mean/norm/id-add — z-batched.
// ===========================================================================
struct MJob {
    const float* xi;
    const float* xt;
    const float* idemb;
    float* outp;
    float* outr;    // optional rounded copy
    int M;
};
struct MJobs2 { MJob j[2]; };

__global__ __launch_bounds__(256) void mhsa_kernel(
    MJobs2 P,
    const float* __restrict__ wq, const float* __restrict__ wk,
    const float* __restrict__ wcat)
{
    const MJob jb = P.j[blockIdx.z];
    const float* __restrict__ xi = jb.xi;
    const float* __restrict__ xt = jb.xt;
    const float* __restrict__ idemb = jb.idemb;
    float* __restrict__ outp = jb.outp;
    float* __restrict__ outr = jb.outr;
    const int M = jb.M;

    __shared__ float sx[8][2][64];
    __shared__ float sqk[8][4][64];
    __shared__ float satt[8][16];
    const int warp = threadIdx.x >> 5;
    const int lane = threadIdx.x & 31;
    const int gw = blockIdx.x * 8 + warp;
    const int nw = gridDim.x * 8;

    for (int n = gw; n < M; n += nw) {
        sx[warp][0][lane]      = xi[(size_t)n * 64 + lane];
        sx[warp][0][lane + 32] = xi[(size_t)n * 64 + lane + 32];
        sx[warp][1][lane]      = xt[(size_t)n * 64 + lane];
        sx[warp][1][lane + 32] = xt[(size_t)n * 64 + lane + 32];
        __syncwarp();

        float qi0=0,qi1=0,ki0=0,ki1=0,qt0=0,qt1=0,kt0=0,kt1=0;
        float pi[4][2] = {}, pt[4][2] = {};
#pragma unroll 4
        for (int k = 0; k < 64; k++) {
            float xik = sx[warp][0][k];
            float xtk = sx[warp][1][k];
            float wq0 = wq[k * 64 + lane],      wq1 = wq[k * 64 + lane + 32];
            float wk0 = wk[k * 64 + lane],      wk1 = wk[k * 64 + lane + 32];
            qi0 = fmaf(xik, wq0, qi0); qi1 = fmaf(xik, wq1, qi1);
            ki0 = fmaf(xik, wk0, ki0); ki1 = fmaf(xik, wk1, ki1);
            qt0 = fmaf(xtk, wq0, qt0); qt1 = fmaf(xtk, wq1, qt1);
            kt0 = fmaf(xtk, wk0, kt0); kt1 = fmaf(xtk, wk1, kt1);
#pragma unroll
            for (int h = 0; h < 4; h++) {
                float wc0 = wcat[(h * 64 + k) * 64 + lane];
                float wc1 = wcat[(h * 64 + k) * 64 + lane + 32];
                pi[h][0] = fmaf(xik, wc0, pi[h][0]);
                pi[h][1] = fmaf(xik, wc1, pi[h][1]);
                pt[h][0] = fmaf(xtk, wc0, pt[h][0]);
                pt[h][1] = fmaf(xtk, wc1, pt[h][1]);
            }
        }
        sqk[warp][0][lane] = qi0; sqk[warp][0][lane + 32] = qi1;
        sqk[warp][1][lane] = ki0; sqk[warp][1][lane + 32] = ki1;
        sqk[warp][2][lane] = qt0; sqk[warp][2][lane + 32] = qt1;
        sqk[warp][3][lane] = kt0; sqk[warp][3][lane + 32] = kt1;
        __syncwarp();

        {
            int cc = lane & 15;
            int h = cc >> 2, a = (cc >> 1) & 1, b = cc & 1;
            const float* qv = &sqk[warp][a * 2][h * 16];
            const float* kv = &sqk[warp][1 + b * 2][h * 16];
            float l = 0.f;
#pragma unroll
            for (int u = 0; u < 16; u++) l = fmaf(qv[u], kv[u], l);
            l *= 0.25f;
            float lo = __shfl_xor_sync(0xffffffffu, l, 1);
            float mm = fmaxf(l, lo);
            float e  = expf(l - mm);
            float eo = __shfl_xor_sync(0xffffffffu, e, 1);
            float att = e / (e + eo);
            if (lane < 16) satt[warp][lane] = att;
        }
        __syncwarp();

        float z0 = 0.f, z1 = 0.f;
#pragma unroll
        for (int h = 0; h < 4; h++) {
            float cih = 0.5f * (satt[warp][h * 4 + 0] + satt[warp][h * 4 + 2]);
            float cth = 0.5f * (satt[warp][h * 4 + 1] + satt[warp][h * 4 + 3]);
            z0 = fmaf(cih, pi[h][0], fmaf(cth, pt[h][0], z0));
            z1 = fmaf(cih, pi[h][1], fmaf(cth, pt[h][1], z1));
        }
        float ss = z0 * z0 + z1 * z1;
#pragma unroll
        for (int o = 16; o; o >>= 1) ss += __shfl_xor_sync(0xffffffffu, ss, o);
        float scale = ID_CAT / fmaxf(sqrtf(ss), 1e-12f);
        float r0 = idemb[(size_t)n * 64 + lane]      + z0 * scale;
        float r1 = idemb[(size_t)n * 64 + lane + 32] + z1 * scale;
        outp[(size_t)n * 64 + lane]      = r0;
        outp[(size_t)n * 64 + lane + 32] = r1;
        if (outr) {
            outr[(size_t)n * 64 + lane]      = rna_tf32(r0);
            outr[(size_t)n * 64 + lane + 32] = rna_tf32(r1);
        }
        __syncwarp();
    }
}

// row softmax; optional rounded copy
__global__ __launch_bounds__(256) void softmax_kernel(
    float* __restrict__ X, float* __restrict__ outr, int M)
{
    const int warp = threadIdx.x >> 5;
    const int lane = threadIdx.x & 31;
    const int gw = blockIdx.x * 8 + warp;
    const int nw = gridDim.x * 8;
    for (int n = gw; n < M; n += nw) {
        size_t i = (size_t)n * 64 + lane;
        float v0 = X[i], v1 = X[i + 32];
        float m = fmaxf(v0, v1);
#pragma unroll
        for (int o = 16; o; o >>= 1) m = fmaxf(m, __shfl_xor_sync(0xffffffffu, m, o));
        float e0 = expf(v0 - m), e1 = expf(v1 - m);
        float s = e0 + e1;
#pragma unroll
        for (int o = 16; o; o >>= 1) s += __shfl_xor_sync(0xffffffffu, s, o);
        float inv = 1.0f / s;
        float r0 = e0 * inv, r1 = e1 * inv;
        X[i] = r0;
        X[i + 32] = r1;
        if (outr) {
            outr[i] = rna_tf32(r0);
            outr[i + 32] = rna_tf32(r1);
        }
    }
}

// final combine — z-batched (user job + item job)
struct EJob {
    const float* g0; const float* g1; const float* g2;
    const float* fA; const float* fB;
    float* o1; float* o2;
    int M;
};
struct EJobs2 { EJob j[2]; };

__global__ __launch_bounds__(256) void epilogue_kernel(EJobs2 P)
{
    const EJob jb = P.j[blockIdx.z];
    const int warp = threadIdx.x >> 5;
    const int lane = threadIdx.x & 31;
    const int gw = blockIdx.x * 8 + warp;
    const int nw = gridDim.x * 8;
    for (int n = gw; n < jb.M; n += nw) {
        size_t i = (size_t)n * 64 + lane;
        size_t i2 = i + 32;
        float m0 = (jb.g0[i]  + jb.g1[i]  + jb.g2[i])  * (1.0f / 3.0f);
        float m1 = (jb.g0[i2] + jb.g1[i2] + jb.g2[i2]) * (1.0f / 3.0f);
        float a0 = jb.fA[i], a1 = jb.fA[i2];
        float ssa = a0 * a0 + a1 * a1;
#pragma unroll
        for (int o = 16; o; o >>= 1) ssa += __shfl_xor_sync(0xffffffffu, ssa, o);
        float sA = MODEL_CAT / fmaxf(sqrtf(ssa), 1e-12f);
        float b0 = jb.fB[i], b1 = jb.fB[i2];
        float ssb = b0 * b0 + b1 * b1;
#pragma unroll
        for (int o = 16; o; o >>= 1) ssb += __shfl_xor_sync(0xffffffffu, ssb, o);
        float sB = MODEL_CAT / fmaxf(sqrtf(ssb), 1e-12f);
        float r0 = m0 + a0 * sA + b0 * sB;
        float r1 = m1 + a1 * sA + b1 * sB;
        jb.o1[i] = r0;  jb.o1[i2] = r1;
        jb.o2[i] = r0;  jb.o2[i2] = r1;
    }
}

// ===========================================================================
extern "C" void kernel_launch(void* const* d_in, const int* in_sizes, int n_in,
                              void* d_out, int out_size)
{
    const float* ui      = (const float*)d_in[0];
    const float* iu      = (const float*)d_in[1];
    const float* img_ui  = (const float*)d_in[2];
    const float* img_iu  = (const float*)d_in[3];
    const float* txt_ui  = (const float*)d_in[4];
    const float* txt_iu  = (const float*)d_in[5];
    const float* imgF    = (const float*)d_in[6];
    const float* txtF    = (const float*)d_in[7];
    const float* W_img   = (const float*)d_in[8];
    const float* b_img   = (const float*)d_in[9];
    const float* W_txt   = (const float*)d_in[10];
    const float* b_txt   = (const float*)d_in[11];
    const float* uid     = (const float*)d_in[12];
    const float* iid     = (const float*)d_in[13];
    const float* w_q     = (const float*)d_in[14];
    const float* w_k     = (const float*)d_in[15];
    const float* w_cat   = (const float*)d_in[16];
    float* out = (float*)d_out;

    float* scr = nullptr;
    cudaGetSymbolAddress((void**)&scr, g_scratch);

    cudaFuncSetAttribute(gemm_cp, cudaFuncAttributeMaxDynamicSharedMemorySize,
                         (int)GEMM_SMEM);
    cudaFuncSetAttribute(gemm128, cudaFuncAttributeMaxDynamicSharedMemorySize,
                         (int)SMEM128);

    // zero atomic-accumulation targets (d_out is poisoned)
    cudaMemsetAsync(out, 0, (size_t)4194304 * sizeof(float));
    cudaMemsetAsync(scr, 0, S_ZERO_END * sizeof(float));

    // prep: round static B operands (one batched launch)
    RJobs4 R;
    R.j[0] = RJob{W_img, scr + S_RWIMG, 262144};
    R.j[1] = RJob{W_txt, scr + S_RWTXT, 65536};
    R.j[2] = RJob{iid,   scr + S_RIID,  262144};
    R.j[3] = RJob{uid,   scr + S_RUID,  524288};
    round_batch<<<dim3(128, 1, 4), 256>>>(R);

    // MEGA launch: G1 (projections) + G4a + G4b (id propagations), 6 jobs
    GJobs6 P;
    P.j[0] = GJob{imgF,   scr + S_RWIMG, b_img, scr + S_IMGF,   IDIM, 4096};
    P.j[1] = GJob{txtF,   scr + S_RWTXT, b_txt, scr + S_TXTF,   IDIM, 1024};
    P.j[2] = GJob{img_ui, scr + S_RIID, nullptr, out + OFF_IUID, UDIM, 4096};
    P.j[3] = GJob{txt_ui, scr + S_RIID, nullptr, out + OFF_TUID, UDIM, 4096};
    P.j[4] = GJob{img_iu, scr + S_RUID, nullptr, scr + S_IIID,   IDIM, 8192};
    P.j[5] = GJob{txt_iu, scr + S_RUID, nullptr, scr + S_TIID,   IDIM, 8192};
    gemm_cp<<<dim3(64, 4, 6), 128, GEMM_SMEM>>>(P);

    // round img_f|txt_f in place (contiguous)
    R.j[0] = RJob{scr + S_IMGF, scr + S_IMGF, 524288};
    round_batch<<<dim3(512, 1, 1), 256>>>(R);

    // G2: [imageUF|textUF] = ui @ [img_f|txt_f]  (ui read once)
    gemm128<<<dim3(64, 8, 1), 256, SMEM128>>>(
        G128{ui, scr + S_IMGF, scr + S_TXTF, out + OFF_IUF, out + OFF_TUF,
             UDIM, 4096});

    // rounded copies of UF for G3's B (contiguous in out)
    R.j[0] = RJob{out + OFF_IUF, scr + S_RB3, 1048576};
    round_batch<<<dim3(512, 1, 1), 256>>>(R);

    // G3: [imageIF|textIF] = iu @ [imageUF|textUF]  (iu read once)
    gemm128<<<dim3(32, 16, 1), 256, SMEM128>>>(
        G128{iu, scr + S_RB3, scr + S_RB3 + 524288, out + OFF_IIF, out + OFF_TIF,
             IDIM, 8192});

    // MHSA (both modality-attention jobs in ONE launch)
    MJobs2 MB;
    MB.j[0] = MJob{out + OFF_IUID, out + OFF_TUID, uid, scr + S_UG0, nullptr, UDIM};
    MB.j[1] = MJob{scr + S_IIID,   scr + S_TIID,   iid, scr + S_IG0, scr + S_RIG0, IDIM};
    mhsa_kernel<<<dim3(512, 1, 2), 256>>>(MB, w_q, w_k, w_cat);

    // propagation loop (N_UI = 2)
    P.j[0] = GJob{ui, scr + S_RIG0, nullptr, scr + S_UG1, UDIM, 4096};
    gemm_cp<<<dim3(64, 8, 1), 128, GEMM_SMEM>>>(P);
    R.j[0] = RJob{scr + S_UG1, scr + S_RUG1, 524288};
    round_batch<<<dim3(512, 1, 1), 256>>>(R);

    P.j[0] = GJob{iu, scr + S_RUG1, nullptr, scr + S_IG1, IDIM, 8192};
    gemm_cp<<<dim3(32, 16, 1), 128, GEMM_SMEM>>>(P);
    R.j[0] = RJob{scr + S_IG1, scr + S_RIG1, 262144};
    round_batch<<<dim3(256, 1, 1), 256>>>(R);

    P.j[0] = GJob{ui, scr + S_RIG1, nullptr, scr + S_UG2, UDIM, 4096};
    gemm_cp<<<dim3(64, 8, 1), 128, GEMM_SMEM>>>(P);
    softmax_kernel<<<1024, 256>>>(scr + S_UG2, scr + S_RUG2, UDIM);

    P.j[0] = GJob{iu, scr + S_RUG2, nullptr, scr + S_IG2, IDIM, 8192};
    gemm_cp<<<dim3(32, 16, 1), 128, GEMM_SMEM>>>(P);
    softmax_kernel<<<512, 256>>>(scr + S_IG2, nullptr, IDIM);

    // final combine (both jobs in ONE launch)
    EJobs2 E;
    E.j[0] = EJob{scr + S_UG0, scr + S_UG1, scr + S_UG2,
                  out + OFF_IUF, out + OFF_TUF,
                  out + OFF_UG_A, out + OFF_UG_B, UDIM};
    E.j[1] = EJob{scr + S_IG0, scr + S_IG1, scr + S_IG2,
                  out + OFF_IIF, out + OFF_TIF,
                  out + OFF_IG_A, out + OFF_IG_B, IDIM};
    epilogue_kernel<<<dim3(512, 1, 2), 256>>>(E);
}

// round 9
// speedup vs baseline: 1.3391x; 1.0216x over previous
#include <cuda_runtime.h>
#include <math.h>
#include <stdint.h>

// ===========================================================================
// MMSSL forward — tf32 mma.sync + cp.async.
//  - gemm_cp: R5-proven 2-stage core (N=64, 128 thr, 4 CTAs/SM)
//  - gemm128: 3-stage cp.async, single barrier per ktile (latency-bound fix)
//  - mega-launch split-K y=8 for finer load balance
// ===========================================================================

#define UDIM 8192
#define IDIM 4096

static constexpr float MODEL_CAT = 0.55f;
static constexpr float ID_CAT    = 0.36f;

// ---- output offsets (floats) ----
static constexpr size_t OFF_UG_A  = 0;
static constexpr size_t OFF_IG_A  = 524288;
static constexpr size_t OFF_IIF   = 786432;
static constexpr size_t OFF_TIF   = 1048576;
static constexpr size_t OFF_IUF   = 1310720;
static constexpr size_t OFF_TUF   = 1835008;
static constexpr size_t OFF_UG_B  = 2359296;
static constexpr size_t OFF_IG_B  = 2883584;
static constexpr size_t OFF_IUID  = 3145728;
static constexpr size_t OFF_TUID  = 3670016;

// ---- scratch (floats); [0, S_ZERO_END) is atomic-accumulated, zeroed ----
static constexpr size_t S_IMGF  = 0;
static constexpr size_t S_TXTF  = 262144;
static constexpr size_t S_IIID  = 524288;
static constexpr size_t S_TIID  = 786432;
static constexpr size_t S_UG1   = 1048576;
static constexpr size_t S_UG2   = 1572864;
static constexpr size_t S_IG1   = 2097152;
static constexpr size_t S_IG2   = 2359296;
static constexpr size_t S_ZERO_END = 2621440;
static constexpr size_t S_UG0   = 2621440;
static constexpr size_t S_IG0   = 3145728;
// rounded-B buffers
static constexpr size_t S_RWIMG = 3407872;
static constexpr size_t S_RWTXT = 3670016;
static constexpr size_t S_RIID  = 3735552;
static constexpr size_t S_RUID  = 3997696;
static constexpr size_t S_RB3   = 4521984;
static constexpr size_t S_RIG0  = 5570560;
static constexpr size_t S_RUG1  = 5832704;
static constexpr size_t S_RIG1  = 6356992;
static constexpr size_t S_RUG2  = 6881280;
static constexpr size_t S_TOTAL = 7405568;

__device__ float g_scratch[S_TOTAL];

// ===========================================================================
__device__ __forceinline__ float rna_tf32(float x) {
    float r;
    asm("cvt.rna.tf32.f32 %0, %1;" : "=f"(r) : "f"(x));
    return r;
}
__device__ __forceinline__ uint32_t s2u(const void* p) {
    uint32_t a;
    asm("{ .reg .u64 t; cvta.to.shared.u64 t, %1; cvt.u32.u64 %0, t; }"
        : "=r"(a) : "l"(p));
    return a;
}
__device__ __forceinline__ void cp16(uint32_t s, const void* g) {
    asm volatile("cp.async.cg.shared.global [%0], [%1], 16;"
                 :: "r"(s), "l"(g) : "memory");
}
__device__ __forceinline__ float lds_f(uint32_t a) {
    float v;
    asm volatile("ld.shared.f32 %0, [%1];" : "=f"(v) : "r"(a));
    return v;
}
__device__ __forceinline__ void mma8(float* d,
                                     uint32_t a0, uint32_t a1, uint32_t a2, uint32_t a3,
                                     uint32_t b0, uint32_t b1) {
    asm volatile(
        "mma.sync.aligned.m16n8k8.row.col.f32.tf32.tf32.f32 "
        "{%0,%1,%2,%3}, {%4,%5,%6,%7}, {%8,%9}, {%0,%1,%2,%3};\n"
        : "+f"(d[0]), "+f"(d[1]), "+f"(d[2]), "+f"(d[3])
        : "r"(a0), "r"(a1), "r"(a2), "r"(a3), "r"(b0), "r"(b1));
}

// ===========================================================================
// GEMM (R5-proven): C[M,64] += rna(A[M,K]) @ B_r[K,64]
// ===========================================================================
struct GJob {
    const float* A;
    const float* B;
    const float* bias;
    float* C;
    int M;
    int K;
};
struct GJobs6 { GJob j[6]; };

static constexpr uint32_t ABUF_B  = 128u * 144u;          // 18432
static constexpr uint32_t BBUF_B  = 32u * 288u;           // 9216
static constexpr uint32_t STAGE_B = ABUF_B + BBUF_B;      // 27648
static constexpr uint32_t GEMM_SMEM = 2u * STAGE_B;       // 55296

__global__ __launch_bounds__(128, 4) void gemm_cp(GJobs6 P)
{
    extern __shared__ char sm[];
    const GJob jb = P.j[blockIdx.z];
    const int mb = blockIdx.x * 128;
    if (mb >= jb.M) return;
    const int K = jb.K;
    const int chunk = K / (int)gridDim.y;
    const int k0 = (int)blockIdx.y * chunk;
    const int nt = chunk >> 5;

    const int tid  = threadIdx.x;
    const int lane = tid & 31;
    const int wid  = tid >> 5;
    const int gid  = lane >> 2;
    const int tig  = lane & 3;
    const int wm   = (wid & 1) * 64;
    const int wn   = (wid >> 1) * 32;

    const uint32_t sb = s2u(sm);
    const float* __restrict__ Ag = jb.A + (size_t)mb * K + k0;
    const float* __restrict__ Bg = jb.B + (size_t)k0 * 64;

    float acc[4][4][4];
#pragma unroll
    for (int m = 0; m < 4; m++)
#pragma unroll
        for (int j = 0; j < 4; j++)
#pragma unroll
            for (int c = 0; c < 4; c++) acc[m][j][c] = 0.f;

    auto LOAD = [&](int t, int buf) {
        const uint32_t ab = sb + (uint32_t)buf * STAGE_B;
        const uint32_t bb = ab + ABUF_B;
        const float* At = Ag + t * 32;
        const float* Bt = Bg + (size_t)t * 32 * 64;
#pragma unroll
        for (int i = 0; i < 8; i++) {
            int c = i * 128 + tid;
            int row = c >> 3, seg = c & 7;
            cp16(ab + (uint32_t)(row * 144 + seg * 16),
                 At + (size_t)row * K + seg * 4);
        }
#pragma unroll
        for (int i = 0; i < 4; i++) {
            int c = i * 128 + tid;
            int k = c >> 4, seg = c & 15;
            cp16(bb + (uint32_t)(k * 288 + seg * 16),
                 Bt + (size_t)k * 64 + seg * 4);
        }
        asm volatile("cp.async.commit_group;" ::: "memory");
    };

    auto COMP = [&](int buf) {
        const uint32_t ab = sb + (uint32_t)buf * STAGE_B;
        const uint32_t bb = ab + ABUF_B;
#pragma unroll
        for (int ks = 0; ks < 4; ks++) {
            uint32_t a0[4], a1[4], a2[4], a3[4];
            const int k = ks * 8 + tig;
#pragma unroll
            for (int mt = 0; mt < 4; mt++) {
                int row = wm + mt * 16 + gid;
                float x0 = lds_f(ab + (uint32_t)((row * 36 + k) << 2));
                float x1 = lds_f(ab + (uint32_t)(((row + 8) * 36 + k) << 2));
                float x2 = lds_f(ab + (uint32_t)((row * 36 + k + 4) << 2));
                float x3 = lds_f(ab + (uint32_t)(((row + 8) * 36 + k + 4) << 2));
                a0[mt] = __float_as_uint(rna_tf32(x0));
                a1[mt] = __float_as_uint(rna_tf32(x1));
                a2[mt] = __float_as_uint(rna_tf32(x2));
                a3[mt] = __float_as_uint(rna_tf32(x3));
            }
#pragma unroll
            for (int j = 0; j < 4; j++) {
                int col = wn + j * 8 + gid;
                uint32_t b0 = __float_as_uint(
                    lds_f(bb + (uint32_t)(((ks * 8 + tig) * 72 + col) << 2)));
                uint32_t b1 = __float_as_uint(
                    lds_f(bb + (uint32_t)(((ks * 8 + tig + 4) * 72 + col) << 2)));
#pragma unroll
                for (int mt = 0; mt < 4; mt++)
                    mma8(acc[mt][j], a0[mt], a1[mt], a2[mt], a3[mt], b0, b1);
            }
        }
    };

    LOAD(0, 0);
    for (int t = 0; t < nt; t++) {
        const int buf = t & 1;
        if (t + 1 < nt) {
            LOAD(t + 1, buf ^ 1);
            asm volatile("cp.async.wait_group 1;" ::: "memory");
        } else {
            asm volatile("cp.async.wait_group 0;" ::: "memory");
        }
        __syncthreads();
        COMP(buf);
        __syncthreads();
    }

    const bool addb = (blockIdx.y == 0) && (jb.bias != nullptr);
#pragma unroll
    for (int mt = 0; mt < 4; mt++) {
#pragma unroll
        for (int j = 0; j < 4; j++) {
            int row = mb + wm + mt * 16 + gid;
            int col = wn + j * 8 + 2 * tig;
            float b0 = addb ? jb.bias[col] : 0.f;
            float b1 = addb ? jb.bias[col + 1] : 0.f;
            atomicAdd(jb.C + (size_t)row * 64 + col,           acc[mt][j][0] + b0);
            atomicAdd(jb.C + (size_t)row * 64 + col + 1,       acc[mt][j][1] + b1);
            atomicAdd(jb.C + (size_t)(row + 8) * 64 + col,     acc[mt][j][2] + b0);
            atomicAdd(jb.C + (size_t)(row + 8) * 64 + col + 1, acc[mt][j][3] + b1);
        }
    }
}

// ---------------- N=128 GEMM: 3-stage cp.async, one barrier per ktile ------
struct G128 {
    const float* A;
    const float* B1;
    const float* B2;
    float* C1;
    float* C2;
    int M;
    int K;
};

static constexpr uint32_t B128_B   = 32u * 544u;            // [32][136] f32
static constexpr uint32_t STAGE128 = ABUF_B + B128_B;       // 35840
static constexpr uint32_t SMEM128  = 3u * STAGE128;         // 107520

__global__ __launch_bounds__(256, 2) void gemm128(G128 jb)
{
    extern __shared__ char sm[];
    const int mb = blockIdx.x * 128;
    const int K = jb.K;
    const int chunk = K / (int)gridDim.y;
    const int k0 = (int)blockIdx.y * chunk;
    const int nt = chunk >> 5;

    const int tid  = threadIdx.x;
    const int lane = tid & 31;
    const int wid  = tid >> 5;
    const int gid  = lane >> 2;
    const int tig  = lane & 3;
    const int wm   = (wid & 1) * 64;
    const int wn   = (wid >> 1) * 32;

    const uint32_t sb = s2u(sm);
    const float* __restrict__ Ag = jb.A + (size_t)mb * K + k0;

    float acc[4][4][4];
#pragma unroll
    for (int m = 0; m < 4; m++)
#pragma unroll
        for (int j = 0; j < 4; j++)
#pragma unroll
            for (int c = 0; c < 4; c++) acc[m][j][c] = 0.f;

    auto LOAD = [&](int t, int buf) {
        const uint32_t ab = sb + (uint32_t)buf * STAGE128;
        const uint32_t bb = ab + ABUF_B;
        const float* At = Ag + t * 32;
#pragma unroll
        for (int i = 0; i < 4; i++) {
            int c = i * 256 + tid;
            int row = c >> 3, seg = c & 7;
            cp16(ab + (uint32_t)(row * 144 + seg * 16),
                 At + (size_t)row * K + seg * 4);
        }
#pragma unroll
        for (int i = 0; i < 4; i++) {
            int c = i * 256 + tid;
            int k = c >> 5, seg = c & 31;
            const float* src = (seg < 16)
                ? (jb.B1 + (size_t)(k0 + t * 32 + k) * 64 + seg * 4)
                : (jb.B2 + (size_t)(k0 + t * 32 + k) * 64 + (seg - 16) * 4);
            cp16(bb + (uint32_t)(k * 544 + seg * 16), src);
        }
        asm volatile("cp.async.commit_group;" ::: "memory");
    };

    auto COMP = [&](int buf) {
        const uint32_t ab = sb + (uint32_t)buf * STAGE128;
        const uint32_t bb = ab + ABUF_B;
#pragma unroll
        for (int ks = 0; ks < 4; ks++) {
            uint32_t a0[4], a1[4], a2[4], a3[4];
            const int k = ks * 8 + tig;
#pragma unroll
            for (int mt = 0; mt < 4; mt++) {
                int row = wm + mt * 16 + gid;
                float x0 = lds_f(ab + (uint32_t)((row * 36 + k) << 2));
                float x1 = lds_f(ab + (uint32_t)(((row + 8) * 36 + k) << 2));
                float x2 = lds_f(ab + (uint32_t)((row * 36 + k + 4) << 2));
                float x3 = lds_f(ab + (uint32_t)(((row + 8) * 36 + k + 4) << 2));
                a0[mt] = __float_as_uint(rna_tf32(x0));
                a1[mt] = __float_as_uint(rna_tf32(x1));
                a2[mt] = __float_as_uint(rna_tf32(x2));
                a3[mt] = __float_as_uint(rna_tf32(x3));
            }
#pragma unroll
            for (int j = 0; j < 4; j++) {
                int col = wn + j * 8 + gid;
                uint32_t b0 = __float_as_uint(
                    lds_f(bb + (uint32_t)(((ks * 8 + tig) * 136 + col) << 2)));
                uint32_t b1 = __float_as_uint(
                    lds_f(bb + (uint32_t)(((ks * 8 + tig + 4) * 136 + col) << 2)));
#pragma unroll
                for (int mt = 0; mt < 4; mt++)
                    mma8(acc[mt][j], a0[mt], a1[mt], a2[mt], a3[mt], b0, b1);
            }
        }
    };

    // 3-stage pipeline, ONE barrier per ktile.
    // top of iter t: pending groups {t, t+1}; LOAD(t+2) writes buf (t-1)%3,
    // whose last reader (COMP(t-1)) finished before this barrier.
    LOAD(0, 0);
    if (nt > 1) LOAD(1, 1);
    int buf = 0;
    for (int t = 0; t < nt; t++) {
        if (t + 2 < nt) {
            asm volatile("cp.async.wait_group 1;" ::: "memory");
        } else {
            asm volatile("cp.async.wait_group 0;" ::: "memory");
        }
        __syncthreads();
        if (t + 2 < nt) {
            int nb = buf + 2;
            if (nb >= 3) nb -= 3;
            LOAD(t + 2, nb);
        }
        COMP(buf);
        if (++buf == 3) buf = 0;
    }

#pragma unroll
    for (int mt = 0; mt < 4; mt++) {
#pragma unroll
        for (int j = 0; j < 4; j++) {
            int row = mb + wm + mt * 16 + gid;
            int col = wn + j * 8 + 2 * tig;
            float* C = (col < 64) ? jb.C1 : jb.C2;
            int cc = col & 63;
            atomicAdd(C + (size_t)row * 64 + cc,           acc[mt][j][0]);
            atomicAdd(C + (size_t)row * 64 + cc + 1,       acc[mt][j][1]);
            atomicAdd(C + (size_t)(row + 8) * 64 + cc,     acc[mt][j][2]);
            atomicAdd(C + (size_t)(row + 8) * 64 + cc + 1, acc[mt][j][3]);
        }
    }
}

// ===========================================================================
// batched elementwise RNA round
// ===========================================================================
struct RJob { const float* s; float* d; int n; };
struct RJobs4 { RJob j[4]; };

__global__ __launch_bounds__(256) void round_batch(RJobs4 P)
{
    const RJob jb = P.j[blockIdx.z];
    int i = blockIdx.x * 256 + threadIdx.x;
    int stride = gridDim.x * 256;
    for (; i < jb.n; i += stride) jb.d[i] = rna_tf32(jb.s[i]);
}

// ===========================================================================
// MHSA over the 2-modality axis fused with mean/norm/id-add — z-batched.
// ===========================================================================
struct MJob {
    const float* xi;
    const float* xt;
    const float* idemb;
    float* outp;
    float* outr;
    int M;
};
struct MJobs2 { MJob j[2]; };

__global__ __launch_bounds__(256) void mhsa_kernel(
    MJobs2 P,
    const float* __restrict__ wq, const float* __restrict__ wk,
    const float* __restrict__ wcat)
{
    const MJob jb = P.j[blockIdx.z];
    const float* __restrict__ xi = jb.xi;
    const float* __restrict__ xt = jb.xt;
    const float* __restrict__ idemb = jb.idemb;
    float* __restrict__ outp = jb.outp;
    float* __restrict__ outr = jb.outr;
    const int M = jb.M;

    __shared__ float sx[8][2][64];
    __shared__ float sqk[8][4][64];
    __shared__ float satt[8][16];
    const int warp = threadIdx.x >> 5;
    const int lane = threadIdx.x & 31;
    const int gw = blockIdx.x * 8 + warp;
    const int nw = gridDim.x * 8;

    for (int n = gw; n < M; n += nw) {
        sx[warp][0][lane]      = xi[(size_t)n * 64 + lane];
        sx[warp][0][lane + 32] = xi[(size_t)n * 64 + lane + 32];
        sx[warp][1][lane]      = xt[(size_t)n * 64 + lane];
        sx[warp][1][lane + 32] = xt[(size_t)n * 64 + lane + 32];
        __syncwarp();

        float qi0=0,qi1=0,ki0=0,ki1=0,qt0=0,qt1=0,kt0=0,kt1=0;
        float pi[4][2] = {}, pt[4][2] = {};
#pragma unroll 4
        for (int k = 0; k < 64; k++) {
            float xik = sx[warp][0][k];
            float xtk = sx[warp][1][k];
            float wq0 = wq[k * 64 + lane],      wq1 = wq[k * 64 + lane + 32];
            float wk0 = wk[k * 64 + lane],      wk1 = wk[k * 64 + lane + 32];
            qi0 = fmaf(xik, wq0, qi0); qi1 = fmaf(xik, wq1, qi1);
            ki0 = fmaf(xik, wk0, ki0); ki1 = fmaf(xik, wk1, ki1);
            qt0 = fmaf(xtk, wq0, qt0); qt1 = fmaf(xtk, wq1, qt1);
            kt0 = fmaf(xtk, wk0, kt0); kt1 = fmaf(xtk, wk1, kt1);
#pragma unroll
            for (int h = 0; h < 4; h++) {
                float wc0 = wcat[(h * 64 + k) * 64 + lane];
                float wc1 = wcat[(h * 64 + k) * 64 + lane + 32];
                pi[h][0] = fmaf(xik, wc0, pi[h][0]);
                pi[h][1] = fmaf(xik, wc1, pi[h][1]);
                pt[h][0] = fmaf(xtk, wc0, pt[h][0]);
                pt[h][1] = fmaf(xtk, wc1, pt[h][1]);
            }
        }
        sqk[warp][0][lane] = qi0; sqk[warp][0][lane + 32] = qi1;
        sqk[warp][1][lane] = ki0; sqk[warp][1][lane + 32] = ki1;
        sqk[warp][2][lane] = qt0; sqk[warp][2][lane + 32] = qt1;
        sqk[warp][3][lane] = kt0; sqk[warp][3][lane + 32] = kt1;
        __syncwarp();

        {
            int cc = lane & 15;
            int h = cc >> 2, a = (cc >> 1) & 1, b = cc & 1;
            const float* qv = &sqk[warp][a * 2][h * 16];
            const float* kv = &sqk[warp][1 + b * 2][h * 16];
            float l = 0.f;
#pragma unroll
            for (int u = 0; u < 16; u++) l = fmaf(qv[u], kv[u], l);
            l *= 0.25f;
            float lo = __shfl_xor_sync(0xffffffffu, l, 1);
            float mm = fmaxf(l, lo);
            float e  = expf(l - mm);
            float eo = __shfl_xor_sync(0xffffffffu, e, 1);
            float att = e / (e + eo);
            if (lane < 16) satt[warp][lane] = att;
        }
        __syncwarp();

        float z0 = 0.f, z1 = 0.f;
#pragma unroll
        for (int h = 0; h < 4; h++) {
            float cih = 0.5f * (satt[warp][h * 4 + 0] + satt[warp][h * 4 + 2]);
            float cth = 0.5f * (satt[warp][h * 4 + 1] + satt[warp][h * 4 + 3]);
            z0 = fmaf(cih, pi[h][0], fmaf(cth, pt[h][0], z0));
            z1 = fmaf(cih, pi[h][1], fmaf(cth, pt[h][1], z1));
        }
        float ss = z0 * z0 + z1 * z1;
#pragma unroll
        for (int o = 16; o; o >>= 1) ss += __shfl_xor_sync(0xffffffffu, ss, o);
        float scale = ID_CAT / fmaxf(sqrtf(ss), 1e-12f);
        float r0 = idemb[(size_t)n * 64 + lane]      + z0 * scale;
        float r1 = idemb[(size_t)n * 64 + lane + 32] + z1 * scale;
        outp[(size_t)n * 64 + lane]      = r0;
        outp[(size_t)n * 64 + lane + 32] = r1;
        if (outr) {
            outr[(size_t)n * 64 + lane]      = rna_tf32(r0);
            outr[(size_t)n * 64 + lane + 32] = rna_tf32(r1);
        }
        __syncwarp();
    }
}

// row softmax; optional rounded copy
__global__ __launch_bounds__(256) void softmax_kernel(
    float* __restrict__ X, float* __restrict__ outr, int M)
{
    const int warp = threadIdx.x >> 5;
    const int lane = threadIdx.x & 31;
    const int gw = blockIdx.x * 8 + warp;
    const int nw = gridDim.x * 8;
    for (int n = gw; n < M; n += nw) {
        size_t i = (size_t)n * 64 + lane;
        float v0 = X[i], v1 = X[i + 32];
        float m = fmaxf(v0, v1);
#pragma unroll
        for (int o = 16; o; o >>= 1) m = fmaxf(m, __shfl_xor_sync(0xffffffffu, m, o));
        float e0 = expf(v0 - m), e1 = expf(v1 - m);
        float s = e0 + e1;
#pragma unroll
        for (int o = 16; o; o >>= 1) s += __shfl_xor_sync(0xffffffffu, s, o);
        float inv = 1.0f / s;
        float r0 = e0 * inv, r1 = e1 * inv;
        X[i] = r0;
        X[i + 32] = r1;
        if (outr) {
            outr[i] = rna_tf32(r0);
            outr[i + 32] = rna_tf32(r1);
        }
    }
}

// final combine — z-batched (user job + item job)
struct EJob {
    const float* g0; const float* g1; const float* g2;
    const float* fA; const float* fB;
    float* o1; float* o2;
    int M;
};
struct EJobs2 { EJob j[2]; };

__global__ __launch_bounds__(256) void epilogue_kernel(EJobs2 P)
{
    const EJob jb = P.j[blockIdx.z];
    const int warp = threadIdx.x >> 5;
    const int lane = threadIdx.x & 31;
    const int gw = blockIdx.x * 8 + warp;
    const int nw = gridDim.x * 8;
    for (int n = gw; n < jb.M; n += nw) {
        size_t i = (size_t)n * 64 + lane;
        size_t i2 = i + 32;
        float m0 = (jb.g0[i]  + jb.g1[i]  + jb.g2[i])  * (1.0f / 3.0f);
        float m1 = (jb.g0[i2] + jb.g1[i2] + jb.g2[i2]) * (1.0f / 3.0f);
        float a0 = jb.fA[i], a1 = jb.fA[i2];
        float ssa = a0 * a0 + a1 * a1;
#pragma unroll
        for (int o = 16; o; o >>= 1) ssa += __shfl_xor_sync(0xffffffffu, ssa, o);
        float sA = MODEL_CAT / fmaxf(sqrtf(ssa), 1e-12f);
        float b0 = jb.fB[i], b1 = jb.fB[i2];
        float ssb = b0 * b0 + b1 * b1;
#pragma unroll
        for (int o = 16; o; o >>= 1) ssb += __shfl_xor_sync(0xffffffffu, ssb, o);
        float sB = MODEL_CAT / fmaxf(sqrtf(ssb), 1e-12f);
        float r0 = m0 + a0 * sA + b0 * sB;
        float r1 = m1 + a1 * sA + b1 * sB;
        jb.o1[i] = r0;  jb.o1[i2] = r1;
        jb.o2[i] = r0;  jb.o2[i2] = r1;
    }
}

// ===========================================================================
extern "C" void kernel_launch(void* const* d_in, const int* in_sizes, int n_in,
                              void* d_out, int out_size)
{
    const float* ui      = (const float*)d_in[0];
    const float* iu      = (const float*)d_in[1];
    const float* img_ui  = (const float*)d_in[2];
    const float* img_iu  = (const float*)d_in[3];
    const float* txt_ui  = (const float*)d_in[4];
    const float* txt_iu  = (const float*)d_in[5];
    const float* imgF    = (const float*)d_in[6];
    const float* txtF    = (const float*)d_in[7];
    const float* W_img   = (const float*)d_in[8];
    const float* b_img   = (const float*)d_in[9];
    const float* W_txt   = (const float*)d_in[10];
    const float* b_txt   = (const float*)d_in[11];
    const float* uid     = (const float*)d_in[12];
    const float* iid     = (const float*)d_in[13];
    const float* w_q     = (const float*)d_in[14];
    const float* w_k     = (const float*)d_in[15];
    const float* w_cat   = (const float*)d_in[16];
    float* out = (float*)d_out;

    float* scr = nullptr;
    cudaGetSymbolAddress((void**)&scr, g_scratch);

    cudaFuncSetAttribute(gemm_cp, cudaFuncAttributeMaxDynamicSharedMemorySize,
                         (int)GEMM_SMEM);
    cudaFuncSetAttribute(gemm128, cudaFuncAttributeMaxDynamicSharedMemorySize,
                         (int)SMEM128);

    // zero atomic-accumulation targets (d_out is poisoned)
    cudaMemsetAsync(out, 0, (size_t)4194304 * sizeof(float));
    cudaMemsetAsync(scr, 0, S_ZERO_END * sizeof(float));

    // prep: round static B operands (one batched launch)
    RJobs4 R;
    R.j[0] = RJob{W_img, scr + S_RWIMG, 262144};
    R.j[1] = RJob{W_txt, scr + S_RWTXT, 65536};
    R.j[2] = RJob{iid,   scr + S_RIID,  262144};
    R.j[3] = RJob{uid,   scr + S_RUID,  524288};
    round_batch<<<dim3(128, 1, 4), 256>>>(R);

    // MEGA launch: G1 (projections) + G4a + G4b (id propagations), 6 jobs
    // y=8: K=8192 -> chunk 1024, K=4096 -> 512, K=1024 -> 128 (finer balance)
    GJobs6 P;
    P.j[0] = GJob{imgF,   scr + S_RWIMG, b_img, scr + S_IMGF,   IDIM, 4096};
    P.j[1] = GJob{txtF,   scr + S_RWTXT, b_txt, scr + S_TXTF,   IDIM, 1024};
    P.j[2] = GJob{img_ui, scr + S_RIID, nullptr, out + OFF_IUID, UDIM, 4096};
    P.j[3] = GJob{txt_ui, scr + S_RIID, nullptr, out + OFF_TUID, UDIM, 4096};
    P.j[4] = GJob{img_iu, scr + S_RUID, nullptr, scr + S_IIID,   IDIM, 8192};
    P.j[5] = GJob{txt_iu, scr + S_RUID, nullptr, scr + S_TIID,   IDIM, 8192};
    gemm_cp<<<dim3(64, 8, 6), 128, GEMM_SMEM>>>(P);

    // round img_f|txt_f in place (contiguous)
    R.j[0] = RJob{scr + S_IMGF, scr + S_IMGF, 524288};
    round_batch<<<dim3(512, 1, 1), 256>>>(R);

    // G2: [imageUF|textUF] = ui @ [img_f|txt_f]  (ui read once)
    gemm128<<<dim3(64, 8, 1), 256, SMEM128>>>(
        G128{ui, scr + S_IMGF, scr + S_TXTF, out + OFF_IUF, out + OFF_TUF,
             UDIM, 4096});

    // rounded copies of UF for G3's B (contiguous in out)
    R.j[0] = RJob{out + OFF_IUF, scr + S_RB3, 1048576};
    round_batch<<<dim3(512, 1, 1), 256>>>(R);

    // G3: [imageIF|textIF] = iu @ [imageUF|textUF]  (iu read once)
    gemm128<<<dim3(32, 16, 1), 256, SMEM128>>>(
        G128{iu, scr + S_RB3, scr + S_RB3 + 524288, out + OFF_IIF, out + OFF_TIF,
             IDIM, 8192});

    // MHSA (both modality-attention jobs in ONE launch)
    MJobs2 MB;
    MB.j[0] = MJob{out + OFF_IUID, out + OFF_TUID, uid, scr + S_UG0, nullptr, UDIM};
    MB.j[1] = MJob{scr + S_IIID,   scr + S_TIID,   iid, scr + S_IG0, scr + S_RIG0, IDIM};
    mhsa_kernel<<<dim3(512, 1, 2), 256>>>(MB, w_q, w_k, w_cat);

    // propagation loop (N_UI = 2)
    P.j[0] = GJob{ui, scr + S_RIG0, nullptr, scr + S_UG1, UDIM, 4096};
    gemm_cp<<<dim3(64, 8, 1), 128, GEMM_SMEM>>>(P);
    R.j[0] = RJob{scr + S_UG1, scr + S_RUG1, 524288};
    round_batch<<<dim3(512, 1, 1), 256>>>(R);

    P.j[0] = GJob{iu, scr + S_RUG1, nullptr, scr + S_IG1, IDIM, 8192};
    gemm_cp<<<dim3(32, 16, 1), 128, GEMM_SMEM>>>(P);
    R.j[0] = RJob{scr + S_IG1, scr + S_RIG1, 262144};
    round_batch<<<dim3(256, 1, 1), 256>>>(R);

    P.j[0] = GJob{ui, scr + S_RIG1, nullptr, scr + S_UG2, UDIM, 4096};
    gemm_cp<<<dim3(64, 8, 1), 128, GEMM_SMEM>>>(P);
    softmax_kernel<<<1024, 256>>>(scr + S_UG2, scr + S_RUG2, UDIM);

    P.j[0] = GJob{iu, scr + S_RUG2, nullptr, scr + S_IG2, IDIM, 8192};
    gemm_cp<<<dim3(32, 16, 1), 128, GEMM_SMEM>>>(P);
    softmax_kernel<<<512, 256>>>(scr + S_IG2, nullptr, IDIM);

    // final combine (both jobs in ONE launch)
    EJobs2 E;
    E.j[0] = EJob{scr + S_UG0, scr + S_UG1, scr + S_UG2,
                  out + OFF_IUF, out + OFF_TUF,
                  out + OFF_UG_A, out + OFF_UG_B, UDIM};
    E.j[1] = EJob{scr + S_IG0, scr + S_IG1, scr + S_IG2,
                  out + OFF_IIF, out + OFF_TIF,
                  out + OFF_IG_A, out + OFF_IG_B, IDIM};
    epilogue_kernel<<<dim3(512, 1, 2), 256>>>(E);
}

// round 10
// speedup vs baseline: 1.3922x; 1.0397x over previous
#include <cuda_runtime.h>
#include <math.h>
#include <stdint.h>

// ===========================================================================
// MMSSL forward — tf32 mma.sync + cp.async.
//  - BOTH operands RNA-rounded on the fragment-load path (no pre-round pass,
//    no rounded GMEM copies, 5 fewer launches)
//  - L2-reuse ordering: consumers of the same 128MB graph run back-to-back
//  - gemm_cp: R5-proven 2-stage core; gemm128: 2-stage (measured best)
// ===========================================================================

#define UDIM 8192
#define IDIM 4096

static constexpr float MODEL_CAT = 0.55f;
static constexpr float ID_CAT    = 0.36f;

// ---- output offsets (floats) ----
static constexpr size_t OFF_UG_A  = 0;
static constexpr size_t OFF_IG_A  = 524288;
static constexpr size_t OFF_IIF   = 786432;
static constexpr size_t OFF_TIF   = 1048576;
static constexpr size_t OFF_IUF   = 1310720;
static constexpr size_t OFF_TUF   = 1835008;
static constexpr size_t OFF_UG_B  = 2359296;
static constexpr size_t OFF_IG_B  = 2883584;
static constexpr size_t OFF_IUID  = 3145728;
static constexpr size_t OFF_TUID  = 3670016;

// ---- scratch (floats); [0, S_ZERO_END) is atomic-accumulated, zeroed ----
static constexpr size_t S_IMGF  = 0;
static constexpr size_t S_TXTF  = 262144;
static constexpr size_t S_IIID  = 524288;
static constexpr size_t S_TIID  = 786432;
static constexpr size_t S_UG1   = 1048576;
static constexpr size_t S_UG2   = 1572864;
static constexpr size_t S_IG1   = 2097152;
static constexpr size_t S_IG2   = 2359296;
static constexpr size_t S_ZERO_END = 2621440;
static constexpr size_t S_UG0   = 2621440;
static constexpr size_t S_IG0   = 3145728;
static constexpr size_t S_TOTAL = 3407872;

__device__ float g_scratch[S_TOTAL];

// ===========================================================================
__device__ __forceinline__ float rna_tf32(float x) {
    float r;
    asm("cvt.rna.tf32.f32 %0, %1;" : "=f"(r) : "f"(x));
    return r;
}
__device__ __forceinline__ uint32_t s2u(const void* p) {
    uint32_t a;
    asm("{ .reg .u64 t; cvta.to.shared.u64 t, %1; cvt.u32.u64 %0, t; }"
        : "=r"(a) : "l"(p));
    return a;
}
__device__ __forceinline__ void cp16(uint32_t s, const void* g) {
    asm volatile("cp.async.cg.shared.global [%0], [%1], 16;"
                 :: "r"(s), "l"(g) : "memory");
}
__device__ __forceinline__ float lds_f(uint32_t a) {
    float v;
    asm volatile("ld.shared.f32 %0, [%1];" : "=f"(v) : "r"(a));
    return v;
}
__device__ __forceinline__ void mma8(float* d,
                                     uint32_t a0, uint32_t a1, uint32_t a2, uint32_t a3,
                                     uint32_t b0, uint32_t b1) {
    asm volatile(
        "mma.sync.aligned.m16n8k8.row.col.f32.tf32.tf32.f32 "
        "{%0,%1,%2,%3}, {%4,%5,%6,%7}, {%8,%9}, {%0,%1,%2,%3};\n"
        : "+f"(d[0]), "+f"(d[1]), "+f"(d[2]), "+f"(d[3])
        : "r"(a0), "r"(a1), "r"(a2), "r"(a3), "r"(b0), "r"(b1));
}

// ===========================================================================
// GEMM: C[M,64] += rna(A[M,K]) @ rna(B[K,64])  (both rounded at use)
// ===========================================================================
struct GJob {
    const float* A;
    const float* B;
    const float* bias;
    float* C;
    int M;
    int K;
};
struct GJobs6 { GJob j[6]; };

static constexpr uint32_t ABUF_B  = 128u * 144u;          // 18432
static constexpr uint32_t BBUF_B  = 32u * 288u;           // 9216
static constexpr uint32_t STAGE_B = ABUF_B + BBUF_B;      // 27648
static constexpr uint32_t GEMM_SMEM = 2u * STAGE_B;       // 55296

__global__ __launch_bounds__(128, 4) void gemm_cp(GJobs6 P)
{
    extern __shared__ char sm[];
    const GJob jb = P.j[blockIdx.z];
    const int mb = blockIdx.x * 128;
    if (mb >= jb.M) return;
    const int K = jb.K;
    const int chunk = K / (int)gridDim.y;
    const int k0 = (int)blockIdx.y * chunk;
    const int nt = chunk >> 5;

    const int tid  = threadIdx.x;
    const int lane = tid & 31;
    const int wid  = tid >> 5;
    const int gid  = lane >> 2;
    const int tig  = lane & 3;
    const int wm   = (wid & 1) * 64;
    const int wn   = (wid >> 1) * 32;

    const uint32_t sb = s2u(sm);
    const float* __restrict__ Ag = jb.A + (size_t)mb * K + k0;
    const float* __restrict__ Bg = jb.B + (size_t)k0 * 64;

    float acc[4][4][4];
#pragma unroll
    for (int m = 0; m < 4; m++)
#pragma unroll
        for (int j = 0; j < 4; j++)
#pragma unroll
            for (int c = 0; c < 4; c++) acc[m][j][c] = 0.f;

    auto LOAD = [&](int t, int buf) {
        const uint32_t ab = sb + (uint32_t)buf * STAGE_B;
        const uint32_t bb = ab + ABUF_B;
        const float* At = Ag + t * 32;
        const float* Bt = Bg + (size_t)t * 32 * 64;
#pragma unroll
        for (int i = 0; i < 8; i++) {
            int c = i * 128 + tid;
            int row = c >> 3, seg = c & 7;
            cp16(ab + (uint32_t)(row * 144 + seg * 16),
                 At + (size_t)row * K + seg * 4);
        }
#pragma unroll
        for (int i = 0; i < 4; i++) {
            int c = i * 128 + tid;
            int k = c >> 4, seg = c & 15;
            cp16(bb + (uint32_t)(k * 288 + seg * 16),
                 Bt + (size_t)k * 64 + seg * 4);
        }
        asm volatile("cp.async.commit_group;" ::: "memory");
    };

    auto COMP = [&](int buf) {
        const uint32_t ab = sb + (uint32_t)buf * STAGE_B;
        const uint32_t bb = ab + ABUF_B;
#pragma unroll
        for (int ks = 0; ks < 4; ks++) {
            uint32_t a0[4], a1[4], a2[4], a3[4];
            const int k = ks * 8 + tig;
#pragma unroll
            for (int mt = 0; mt < 4; mt++) {
                int row = wm + mt * 16 + gid;
                float x0 = lds_f(ab + (uint32_t)((row * 36 + k) << 2));
                float x1 = lds_f(ab + (uint32_t)(((row + 8) * 36 + k) << 2));
                float x2 = lds_f(ab + (uint32_t)((row * 36 + k + 4) << 2));
                float x3 = lds_f(ab + (uint32_t)(((row + 8) * 36 + k + 4) << 2));
                a0[mt] = __float_as_uint(rna_tf32(x0));
                a1[mt] = __float_as_uint(rna_tf32(x1));
                a2[mt] = __float_as_uint(rna_tf32(x2));
                a3[mt] = __float_as_uint(rna_tf32(x3));
            }
#pragma unroll
            for (int j = 0; j < 4; j++) {
                int col = wn + j * 8 + gid;
                uint32_t b0 = __float_as_uint(rna_tf32(
                    lds_f(bb + (uint32_t)(((ks * 8 + tig) * 72 + col) << 2))));
                uint32_t b1 = __float_as_uint(rna_tf32(
                    lds_f(bb + (uint32_t)(((ks * 8 + tig + 4) * 72 + col) << 2))));
#pragma unroll
                for (int mt = 0; mt < 4; mt++)
                    mma8(acc[mt][j], a0[mt], a1[mt], a2[mt], a3[mt], b0, b1);
            }
        }
    };

    LOAD(0, 0);
    for (int t = 0; t < nt; t++) {
        const int buf = t & 1;
        if (t + 1 < nt) {
            LOAD(t + 1, buf ^ 1);
            asm volatile("cp.async.wait_group 1;" ::: "memory");
        } else {
            asm volatile("cp.async.wait_group 0;" ::: "memory");
        }
        __syncthreads();
        COMP(buf);
        __syncthreads();
    }

    const bool addb = (blockIdx.y == 0) && (jb.bias != nullptr);
#pragma unroll
    for (int mt = 0; mt < 4; mt++) {
#pragma unroll
        for (int j = 0; j < 4; j++) {
            int row = mb + wm + mt * 16 + gid;
            int col = wn + j * 8 + 2 * tig;
            float b0 = addb ? jb.bias[col] : 0.f;
            float b1 = addb ? jb.bias[col + 1] : 0.f;
            atomicAdd(jb.C + (size_t)row * 64 + col,           acc[mt][j][0] + b0);
            atomicAdd(jb.C + (size_t)row * 64 + col + 1,       acc[mt][j][1] + b1);
            atomicAdd(jb.C + (size_t)(row + 8) * 64 + col,     acc[mt][j][2] + b0);
            atomicAdd(jb.C + (size_t)(row + 8) * 64 + col + 1, acc[mt][j][3] + b1);
        }
    }
}

// ---------------- N=128 GEMM (256 threads, 2-stage — measured best) --------
struct G128 {
    const float* A;
    const float* B1;
    const float* B2;
    float* C1;
    float* C2;
    int M;
    int K;
};

static constexpr uint32_t B128_B   = 32u * 544u;            // [32][136] f32
static constexpr uint32_t STAGE128 = ABUF_B + B128_B;       // 35840
static constexpr uint32_t SMEM128  = 2u * STAGE128;         // 71680

__global__ __launch_bounds__(256, 2) void gemm128(G128 jb)
{
    extern __shared__ char sm[];
    const int mb = blockIdx.x * 128;
    const int K = jb.K;
    const int chunk = K / (int)gridDim.y;
    const int k0 = (int)blockIdx.y * chunk;
    const int nt = chunk >> 5;

    const int tid  = threadIdx.x;
    const int lane = tid & 31;
    const int wid  = tid >> 5;
    const int gid  = lane >> 2;
    const int tig  = lane & 3;
    const int wm   = (wid & 1) * 64;
    const int wn   = (wid >> 1) * 32;

    const uint32_t sb = s2u(sm);
    const float* __restrict__ Ag = jb.A + (size_t)mb * K + k0;

    float acc[4][4][4];
#pragma unroll
    for (int m = 0; m < 4; m++)
#pragma unroll
        for (int j = 0; j < 4; j++)
#pragma unroll
            for (int c = 0; c < 4; c++) acc[m][j][c] = 0.f;

    auto LOAD = [&](int t, int buf) {
        const uint32_t ab = sb + (uint32_t)buf * STAGE128;
        const uint32_t bb = ab + ABUF_B;
        const float* At = Ag + t * 32;
#pragma unroll
        for (int i = 0; i < 4; i++) {
            int c = i * 256 + tid;
            int row = c >> 3, seg = c & 7;
            cp16(ab + (uint32_t)(row * 144 + seg * 16),
                 At + (size_t)row * K + seg * 4);
        }
#pragma unroll
        for (int i = 0; i < 4; i++) {
            int c = i * 256 + tid;
            int k = c >> 5, seg = c & 31;
            const float* src = (seg < 16)
                ? (jb.B1 + (size_t)(k0 + t * 32 + k) * 64 + seg * 4)
                : (jb.B2 + (size_t)(k0 + t * 32 + k) * 64 + (seg - 16) * 4);
            cp16(bb + (uint32_t)(k * 544 + seg * 16), src);
        }
        asm volatile("cp.async.commit_group;" ::: "memory");
    };

    auto COMP = [&](int buf) {
        const uint32_t ab = sb + (uint32_t)buf * STAGE128;
        const uint32_t bb = ab + ABUF_B;
#pragma unroll
        for (int ks = 0; ks < 4; ks++) {
            uint32_t a0[4], a1[4], a2[4], a3[4];
            const int k = ks * 8 + tig;
#pragma unroll
            for (int mt = 0; mt < 4; mt++) {
                int row = wm + mt * 16 + gid;
                float x0 = lds_f(ab + (uint32_t)((row * 36 + k) << 2));
                float x1 = lds_f(ab + (uint32_t)(((row + 8) * 36 + k) << 2));
                float x2 = lds_f(ab + (uint32_t)((row * 36 + k + 4) << 2));
                float x3 = lds_f(ab + (uint32_t)(((row + 8) * 36 + k + 4) << 2));
                a0[mt] = __float_as_uint(rna_tf32(x0));
                a1[mt] = __float_as_uint(rna_tf32(x1));
                a2[mt] = __float_as_uint(rna_tf32(x2));
                a3[mt] = __float_as_uint(rna_tf32(x3));
            }
#pragma unroll
            for (int j = 0; j < 4; j++) {
                int col = wn + j * 8 + gid;
                uint32_t b0 = __float_as_uint(rna_tf32(
                    lds_f(bb + (uint32_t)(((ks * 8 + tig) * 136 + col) << 2))));
                uint32_t b1 = __float_as_uint(rna_tf32(
                    lds_f(bb + (uint32_t)(((ks * 8 + tig + 4) * 136 + col) << 2))));
#pragma unroll
                for (int mt = 0; mt < 4; mt++)
                    mma8(acc[mt][j], a0[mt], a1[mt], a2[mt], a3[mt], b0, b1);
            }
        }
    };

    LOAD(0, 0);
    for (int t = 0; t < nt; t++) {
        const int buf = t & 1;
        if (t + 1 < nt) {
            LOAD(t + 1, buf ^ 1);
            asm volatile("cp.async.wait_group 1;" ::: "memory");
        } else {
            asm volatile("cp.async.wait_group 0;" ::: "memory");
        }
        __syncthreads();
        COMP(buf);
        __syncthreads();
    }

#pragma unroll
    for (int mt = 0; mt < 4; mt++) {
#pragma unroll
        for (int j = 0; j < 4; j++) {
            int row = mb + wm + mt * 16 + gid;
            int col = wn + j * 8 + 2 * tig;
            float* C = (col < 64) ? jb.C1 : jb.C2;
            int cc = col & 63;
            atomicAdd(C + (size_t)row * 64 + cc,           acc[mt][j][0]);
            atomicAdd(C + (size_t)row * 64 + cc + 1,       acc[mt][j][1]);
            atomicAdd(C + (size_t)(row + 8) * 64 + cc,     acc[mt][j][2]);
            atomicAdd(C + (size_t)(row + 8) * 64 + cc + 1, acc[mt][j][3]);
        }
    }
}

// ===========================================================================
// MHSA over the 2-modality axis fused with mean/norm/id-add — z-batched.
// ===========================================================================
struct MJob {
    const float* xi;
    const float* xt;
    const float* idemb;
    float* outp;
    int M;
};
struct MJobs2 { MJob j[2]; };

__global__ __launch_bounds__(256) void mhsa_kernel(
    MJobs2 P,
    const float* __restrict__ wq, const float* __restrict__ wk,
    const float* __restrict__ wcat)
{
    const MJob jb = P.j[blockIdx.z];
    const float* __restrict__ xi = jb.xi;
    const float* __restrict__ xt = jb.xt;
    const float* __restrict__ idemb = jb.idemb;
    float* __restrict__ outp = jb.outp;
    const int M = jb.M;

    __shared__ float sx[8][2][64];
    __shared__ float sqk[8][4][64];
    __shared__ float satt[8][16];
    const int warp = threadIdx.x >> 5;
    const int lane = threadIdx.x & 31;
    const int gw = blockIdx.x * 8 + warp;
    const int nw = gridDim.x * 8;

    for (int n = gw; n < M; n += nw) {
        sx[warp][0][lane]      = xi[(size_t)n * 64 + lane];
        sx[warp][0][lane + 32] = xi[(size_t)n * 64 + lane + 32];
        sx[warp][1][lane]      = xt[(size_t)n * 64 + lane];
        sx[warp][1][lane + 32] = xt[(size_t)n * 64 + lane + 32];
        __syncwarp();

        float qi0=0,qi1=0,ki0=0,ki1=0,qt0=0,qt1=0,kt0=0,kt1=0;
        float pi[4][2] = {}, pt[4][2] = {};
#pragma unroll 4
        for (int k = 0; k < 64; k++) {
            float xik = sx[warp][0][k];
            float xtk = sx[warp][1][k];
            float wq0 = wq[k * 64 + lane],      wq1 = wq[k * 64 + lane + 32];
            float wk0 = wk[k * 64 + lane],      wk1 = wk[k * 64 + lane + 32];
            qi0 = fmaf(xik, wq0, qi0); qi1 = fmaf(xik, wq1, qi1);
            ki0 = fmaf(xik, wk0, ki0); ki1 = fmaf(xik, wk1, ki1);
            qt0 = fmaf(xtk, wq0, qt0); qt1 = fmaf(xtk, wq1, qt1);
            kt0 = fmaf(xtk, wk0, kt0); kt1 = fmaf(xtk, wk1, kt1);
#pragma unroll
            for (int h = 0; h < 4; h++) {
                float wc0 = wcat[(h * 64 + k) * 64 + lane];
                float wc1 = wcat[(h * 64 + k) * 64 + lane + 32];
                pi[h][0] = fmaf(xik, wc0, pi[h][0]);
                pi[h][1] = fmaf(xik, wc1, pi[h][1]);
                pt[h][0] = fmaf(xtk, wc0, pt[h][0]);
                pt[h][1] = fmaf(xtk, wc1, pt[h][1]);
            }
        }
        sqk[warp][0][lane] = qi0; sqk[warp][0][lane + 32] = qi1;
        sqk[warp][1][lane] = ki0; sqk[warp][1][lane + 32] = ki1;
        sqk[warp][2][lane] = qt0; sqk[warp][2][lane + 32] = qt1;
        sqk[warp][3][lane] = kt0; sqk[warp][3][lane + 32] = kt1;
        __syncwarp();

        {
            int cc = lane & 15;
            int h = cc >> 2, a = (cc >> 1) & 1, b = cc & 1;
            const float* qv = &sqk[warp][a * 2][h * 16];
            const float* kv = &sqk[warp][1 + b * 2][h * 16];
            float l = 0.f;
#pragma unroll
            for (int u = 0; u < 16; u++) l = fmaf(qv[u], kv[u], l);
            l *= 0.25f;
            float lo = __shfl_xor_sync(0xffffffffu, l, 1);
            float mm = fmaxf(l, lo);
            float e  = expf(l - mm);
            float eo = __shfl_xor_sync(0xffffffffu, e, 1);
            float att = e / (e + eo);
            if (lane < 16) satt[warp][lane] = att;
        }
        __syncwarp();

        float z0 = 0.f, z1 = 0.f;
#pragma unroll
        for (int h = 0; h < 4; h++) {
            float cih = 0.5f * (satt[warp][h * 4 + 0] + satt[warp][h * 4 + 2]);
            float cth = 0.5f * (satt[warp][h * 4 + 1] + satt[warp][h * 4 + 3]);
            z0 = fmaf(cih, pi[h][0], fmaf(cth, pt[h][0], z0));
            z1 = fmaf(cih, pi[h][1], fmaf(cth, pt[h][1], z1));
        }
        float ss = z0 * z0 + z1 * z1;
#pragma unroll
        for (int o = 16; o; o >>= 1) ss += __shfl_xor_sync(0xffffffffu, ss, o);
        float scale = ID_CAT / fmaxf(sqrtf(ss), 1e-12f);
        outp[(size_t)n * 64 + lane]      = idemb[(size_t)n * 64 + lane]      + z0 * scale;
        outp[(size_t)n * 64 + lane + 32] = idemb[(size_t)n * 64 + lane + 32] + z1 * scale;
        __syncwarp();
    }
}

// row softmax in place
__global__ __launch_bounds__(256) void softmax_kernel(float* __restrict__ X, int M)
{
    const int warp = threadIdx.x >> 5;
    const int lane = threadIdx.x & 31;
    const int gw = blockIdx.x * 8 + warp;
    const int nw = gridDim.x * 8;
    for (int n = gw; n < M; n += nw) {
        size_t i = (size_t)n * 64 + lane;
        float v0 = X[i], v1 = X[i + 32];
        float m = fmaxf(v0, v1);
#pragma unroll
        for (int o = 16; o; o >>= 1) m = fmaxf(m, __shfl_xor_sync(0xffffffffu, m, o));
        float e0 = expf(v0 - m), e1 = expf(v1 - m);
        float s = e0 + e1;
#pragma unroll
        for (int o = 16; o; o >>= 1) s += __shfl_xor_sync(0xffffffffu, s, o);
        float inv = 1.0f / s;
        X[i] = e0 * inv;
        X[i + 32] = e1 * inv;
    }
}

// final combine — z-batched (user job + item job)
struct EJob {
    const float* g0; const float* g1; const float* g2;
    const float* fA; const float* fB;
    float* o1; float* o2;
    int M;
};
struct EJobs2 { EJob j[2]; };

__global__ __launch_bounds__(256) void epilogue_kernel(EJobs2 P)
{
    const EJob jb = P.j[blockIdx.z];
    const int warp = threadIdx.x >> 5;
    const int lane = threadIdx.x & 31;
    const int gw = blockIdx.x * 8 + warp;
    const int nw = gridDim.x * 8;
    for (int n = gw; n < jb.M; n += nw) {
        size_t i = (size_t)n * 64 + lane;
        size_t i2 = i + 32;
        float m0 = (jb.g0[i]  + jb.g1[i]  + jb.g2[i])  * (1.0f / 3.0f);
        float m1 = (jb.g0[i2] + jb.g1[i2] + jb.g2[i2]) * (1.0f / 3.0f);
        float a0 = jb.fA[i], a1 = jb.fA[i2];
        float ssa = a0 * a0 + a1 * a1;
#pragma unroll
        for (int o = 16; o; o >>= 1) ssa += __shfl_xor_sync(0xffffffffu, ssa, o);
        float sA = MODEL_CAT / fmaxf(sqrtf(ssa), 1e-12f);
        float b0 = jb.fB[i], b1 = jb.fB[i2];
        float ssb = b0 * b0 + b1 * b1;
#pragma unroll
        for (int o = 16; o; o >>= 1) ssb += __shfl_xor_sync(0xffffffffu, ssb, o);
        float sB = MODEL_CAT / fmaxf(sqrtf(ssb), 1e-12f);
        float r0 = m0 + a0 * sA + b0 * sB;
        float r1 = m1 + a1 * sA + b1 * sB;
        jb.o1[i] = r0;  jb.o1[i2] = r1;
        jb.o2[i] = r0;  jb.o2[i2] = r1;
    }
}

// ===========================================================================
extern "C" void kernel_launch(void* const* d_in, const int* in_sizes, int n_in,
                              void* d_out, int out_size)
{
    const float* ui      = (const float*)d_in[0];
    const float* iu      = (const float*)d_in[1];
    const float* img_ui  = (const float*)d_in[2];
    const float* img_iu  = (const float*)d_in[3];
    const float* txt_ui  = (const float*)d_in[4];
    const float* txt_iu  = (const float*)d_in[5];
    const float* imgF    = (const float*)d_in[6];
    const float* txtF    = (const float*)d_in[7];
    const float* W_img   = (const float*)d_in[8];
    const float* b_img   = (const float*)d_in[9];
    const float* W_txt   = (const float*)d_in[10];
    const float* b_txt   = (const float*)d_in[11];
    const float* uid     = (const float*)d_in[12];
    const float* iid     = (const float*)d_in[13];
    const float* w_q     = (const float*)d_in[14];
    const float* w_k     = (const float*)d_in[15];
    const float* w_cat   = (const float*)d_in[16];
    float* out = (float*)d_out;

    float* scr = nullptr;
    cudaGetSymbolAddress((void**)&scr, g_scratch);

    cudaFuncSetAttribute(gemm_cp, cudaFuncAttributeMaxDynamicSharedMemorySize,
                         (int)GEMM_SMEM);
    cudaFuncSetAttribute(gemm128, cudaFuncAttributeMaxDynamicSharedMemorySize,
                         (int)SMEM128);

    // zero atomic-accumulation targets (d_out is poisoned)
    cudaMemsetAsync(out, 0, (size_t)4194304 * sizeof(float));
    cudaMemsetAsync(scr, 0, S_ZERO_END * sizeof(float));

    // MEGA launch: G1 (projections) + G4a + G4b (id propagations), 6 jobs.
    // B operands are RAW inputs — rounding happens inside the GEMM.
    GJobs6 P;
    P.j[0] = GJob{imgF,   W_img, b_img,   scr + S_IMGF,   IDIM, 4096};
    P.j[1] = GJob{txtF,   W_txt, b_txt,   scr + S_TXTF,   IDIM, 1024};
    P.j[2] = GJob{img_ui, iid,   nullptr, out + OFF_IUID, UDIM, 4096};
    P.j[3] = GJob{txt_ui, iid,   nullptr, out + OFF_TUID, UDIM, 4096};
    P.j[4] = GJob{img_iu, uid,   nullptr, scr + S_IIID,   IDIM, 8192};
    P.j[5] = GJob{txt_iu, uid,   nullptr, scr + S_TIID,   IDIM, 8192};
    gemm_cp<<<dim3(64, 8, 6), 128, GEMM_SMEM>>>(P);

    // MHSA (both jobs; needs only mega outputs)
    MJobs2 MB;
    MB.j[0] = MJob{out + OFF_IUID, out + OFF_TUID, uid, scr + S_UG0, UDIM};
    MB.j[1] = MJob{scr + S_IIID,   scr + S_TIID,   iid, scr + S_IG0, IDIM};
    mhsa_kernel<<<dim3(512, 1, 2), 256>>>(MB, w_q, w_k, w_cat);

    // --- ui passes back-to-back (L2 reuse on the 128MB graph) ---
    // G2: [imageUF|textUF] = ui @ [img_f|txt_f]
    gemm128<<<dim3(64, 8, 1), 256, SMEM128>>>(
        G128{ui, scr + S_IMGF, scr + S_TXTF, out + OFF_IUF, out + OFF_TUF,
             UDIM, 4096});
    // loop1: UG1 = ui @ i_g0
    P.j[0] = GJob{ui, scr + S_IG0, nullptr, scr + S_UG1, UDIM, 4096};
    gemm_cp<<<dim3(64, 8, 1), 128, GEMM_SMEM>>>(P);

    // --- iu passes back-to-back ---
    // G3: [imageIF|textIF] = iu @ [imageUF|textUF]
    gemm128<<<dim3(32, 16, 1), 256, SMEM128>>>(
        G128{iu, out + OFF_IUF, out + OFF_TUF, out + OFF_IIF, out + OFF_TIF,
             IDIM, 8192});
    // loop2: IG1 = iu @ UG1
    P.j[0] = GJob{iu, scr + S_UG1, nullptr, scr + S_IG1, IDIM, 8192};
    gemm_cp<<<dim3(32, 16, 1), 128, GEMM_SMEM>>>(P);

    // loop3: UG2 = ui @ IG1, then row-softmax
    P.j[0] = GJob{ui, scr + S_IG1, nullptr, scr + S_UG2, UDIM, 4096};
    gemm_cp<<<dim3(64, 8, 1), 128, GEMM_SMEM>>>(P);
    softmax_kernel<<<1024, 256>>>(scr + S_UG2, UDIM);

    // loop4: IG2 = iu @ UG2, then row-softmax
    P.j[0] = GJob{iu, scr + S_UG2, nullptr, scr + S_IG2, IDIM, 8192};
    gemm_cp<<<dim3(32, 16, 1), 128, GEMM_SMEM>>>(P);
    softmax_kernel<<<512, 256>>>(scr + S_IG2, IDIM);

    // final combine (both jobs)
    EJobs2 E;
    E.j[0] = EJob{scr + S_UG0, scr + S_UG1, scr + S_UG2,
                  out + OFF_IUF, out + OFF_TUF,
                  out + OFF_UG_A, out + OFF_UG_B, UDIM};
    E.j[1] = EJob{scr + S_IG0, scr + S_IG1, scr + S_IG2,
                  out + OFF_IIF, out + OFF_TIF,
                  out + OFF_IG_A, out + OFF_IG_B, IDIM};
    epilogue_kernel<<<dim3(512, 1, 2), 256>>>(E);
}